// round 4
// baseline (speedup 1.0000x reference)
#include <cuda_runtime.h>
#include <math.h>
#include <stdint.h>

#define BB 2
#define LL 4096
#define CC 1024
#define NHH 16
#define DHH 64
#define NR 1638
#define QKVW 3072

// ------------------------- scratch (device globals; no runtime alloc) -------
__device__ float g_mean[BB * CC];
__device__ double g_part[BB * 8 * CC];
__device__ float g_mse[BB * LL];
__device__ int g_idx[BB * NR];
__device__ float g_bias[QKVW];
__device__ float g_qkv[(size_t)BB * NR * QKVW];   // (b, i, 3*C)
__device__ float g_q[(size_t)BB * NHH * NR * DHH]; // (b,h,i,d) normalized+rope
__device__ float g_k[(size_t)BB * NHH * NR * DHH];
__device__ float g_o[(size_t)BB * NR * CC];        // attention out, (b,i,h*64+d)
__device__ float g_pr[(size_t)BB * NR * CC];       // proj out

// ------------------------- helpers -----------------------------------------
__device__ __forceinline__ float warpSumF(float v) {
#pragma unroll
    for (int m = 16; m; m >>= 1) v += __shfl_xor_sync(0xffffffffu, v, m);
    return v;
}
__device__ __forceinline__ double warpSumD(double v) {
#pragma unroll
    for (int m = 16; m; m >>= 1) v += __shfl_xor_sync(0xffffffffu, v, m);
    return v;
}

// ------------------------- stage 1: mean over L (fp64 accum) ---------------
__global__ void k_colsum(const float* __restrict__ x) {
    int c = blockIdx.x * 256 + threadIdx.x;
    int b = blockIdx.z;
    int l0 = blockIdx.y * 512;
    const float* p = x + ((size_t)b * LL + l0) * CC + c;
    double a0 = 0, a1 = 0, a2 = 0, a3 = 0;
#pragma unroll 4
    for (int l = 0; l < 512; l += 4) {
        a0 += (double)p[(size_t)(l + 0) * CC];
        a1 += (double)p[(size_t)(l + 1) * CC];
        a2 += (double)p[(size_t)(l + 2) * CC];
        a3 += (double)p[(size_t)(l + 3) * CC];
    }
    g_part[(b * 8 + blockIdx.y) * CC + c] = a0 + a1 + a2 + a3;
}

__global__ void k_meanfin() {
    int i = blockIdx.x * 256 + threadIdx.x; // 0..2047
    int b = i >> 10, c = i & 1023;
    double s = 0;
#pragma unroll
    for (int k = 0; k < 8; k++) s += g_part[(b * 8 + k) * CC + c];
    g_mean[b * CC + c] = (float)(s * (1.0 / (double)LL));
}

// ------------------------- stage 2: per-row mse (fp64 accum) ---------------
__global__ void k_mse(const float* __restrict__ x) {
    int l = blockIdx.x, b = blockIdx.y;
    const float* xr = x + ((size_t)b * LL + l) * CC;
    double acc = 0;
#pragma unroll
    for (int k = 0; k < 4; k++) {
        int c = threadIdx.x + k * 256;
        double d = (double)xr[c] - (double)g_mean[b * CC + c];
        acc += d * d;
    }
    acc = warpSumD(acc);
    __shared__ double red[8];
    if ((threadIdx.x & 31) == 0) red[threadIdx.x >> 5] = acc;
    __syncthreads();
    if (threadIdx.x == 0) {
        double t = 0;
#pragma unroll
        for (int w = 0; w < 8; w++) t += red[w];
        g_mse[b * LL + l] = (float)t;
    }
}

// ------------------------- stage 3: top-NR selection (bitonic, per batch) --
__global__ void k_topk() {
    __shared__ unsigned long long keys[LL];
    int b = blockIdx.x;
    for (int i = threadIdx.x; i < LL; i += blockDim.x) {
        unsigned int fb = __float_as_uint(g_mse[b * LL + i]); // mse >= 0 -> monotonic bits
        keys[i] = ((unsigned long long)fb << 32) | (unsigned int)i;
    }
    __syncthreads();
    for (int k = 2; k <= LL; k <<= 1) {
        for (int j = k >> 1; j > 0; j >>= 1) {
            for (int t = threadIdx.x; t < LL / 2; t += blockDim.x) {
                int i = (t / j) * (2 * j) + (t % j);
                int ixj = i ^ j;
                bool up = ((i & k) == 0); // descending sort overall
                unsigned long long a = keys[i], c = keys[ixj];
                bool sw = up ? (a < c) : (a > c);
                if (sw) { keys[i] = c; keys[ixj] = a; }
            }
            __syncthreads();
        }
    }
    for (int i = threadIdx.x; i < NR; i += blockDim.x)
        g_idx[b * NR + i] = (int)(keys[i] & 0xFFFFFFFFu);
}

// ------------------------- stage 4: fused bias ------------------------------
__global__ void k_bias(const float* __restrict__ qb, const float* __restrict__ vb) {
    int i = blockIdx.x * 256 + threadIdx.x;
    if (i < QKVW) g_bias[i] = (i < CC) ? qb[i] : ((i < 2 * CC) ? 0.f : vb[i - 2 * CC]);
}

// ------------------------- generic NT GEMM: C = A @ W^T + bias -------------
// A: (M,K) row-major (optionally gathered rows via g_idx), W: (N,K) row-major
template <bool GATHER>
__global__ void __launch_bounds__(256) k_gemm(
    const float* __restrict__ A, const float* __restrict__ Wm,
    const float* __restrict__ bias, float* __restrict__ Cg,
    int M, int N, size_t aBatch, size_t cBatch)
{
    const int K = 1024;
    __shared__ float As[16][132];
    __shared__ float Bs[16][132];
    int tid = threadIdx.x;
    int bm = blockIdx.y * 128, bn = blockIdx.x * 128, b = blockIdx.z;
    const float* Ab = A + (size_t)b * aBatch;
    const int* gb = g_idx + b * NR;
    int lr = tid >> 2, lk = (tid & 3) * 4;
    int ty = tid >> 4, tx = tid & 15;

    const float* arow[2];
    bool aval[2];
#pragma unroll
    for (int pass = 0; pass < 2; pass++) {
        int m = bm + pass * 64 + lr;
        aval[pass] = (m < M);
        int src = aval[pass] ? (GATHER ? gb[m] : m) : 0;
        arow[pass] = Ab + (size_t)src * K;
    }
    const float* brow[2];
#pragma unroll
    for (int pass = 0; pass < 2; pass++)
        brow[pass] = Wm + (size_t)(bn + pass * 64 + lr) * K;

    float acc[8][8];
#pragma unroll
    for (int i = 0; i < 8; i++)
#pragma unroll
        for (int j = 0; j < 8; j++) acc[i][j] = 0.f;

    for (int k0 = 0; k0 < K; k0 += 16) {
#pragma unroll
        for (int pass = 0; pass < 2; pass++) {
            int r = pass * 64 + lr;
            float4 v = make_float4(0.f, 0.f, 0.f, 0.f);
            if (aval[pass]) v = *(const float4*)(arow[pass] + k0 + lk);
            As[lk + 0][r] = v.x; As[lk + 1][r] = v.y; As[lk + 2][r] = v.z; As[lk + 3][r] = v.w;
            float4 w = *(const float4*)(brow[pass] + k0 + lk);
            Bs[lk + 0][r] = w.x; Bs[lk + 1][r] = w.y; Bs[lk + 2][r] = w.z; Bs[lk + 3][r] = w.w;
        }
        __syncthreads();
#pragma unroll
        for (int kk = 0; kk < 16; kk++) {
            float4 a0 = *(const float4*)&As[kk][ty * 8];
            float4 a1 = *(const float4*)&As[kk][ty * 8 + 4];
            float4 b0 = *(const float4*)&Bs[kk][tx * 8];
            float4 b1 = *(const float4*)&Bs[kk][tx * 8 + 4];
            float av[8] = {a0.x, a0.y, a0.z, a0.w, a1.x, a1.y, a1.z, a1.w};
            float bv[8] = {b0.x, b0.y, b0.z, b0.w, b1.x, b1.y, b1.z, b1.w};
#pragma unroll
            for (int i = 0; i < 8; i++)
#pragma unroll
                for (int j = 0; j < 8; j++) acc[i][j] += av[i] * bv[j];
        }
        __syncthreads();
    }
    float bv[8];
#pragma unroll
    for (int j = 0; j < 8; j++) bv[j] = bias ? bias[bn + tx * 8 + j] : 0.f;
    float* Cb = Cg + (size_t)b * cBatch;
#pragma unroll
    for (int i = 0; i < 8; i++) {
        int m = bm + ty * 8 + i;
        if (m >= M) continue;
        float4 o0 = make_float4(acc[i][0] + bv[0], acc[i][1] + bv[1], acc[i][2] + bv[2], acc[i][3] + bv[3]);
        float4 o1 = make_float4(acc[i][4] + bv[4], acc[i][5] + bv[5], acc[i][6] + bv[6], acc[i][7] + bv[7]);
        *(float4*)(Cb + (size_t)m * N + bn + tx * 8) = o0;
        *(float4*)(Cb + (size_t)m * N + bn + tx * 8 + 4) = o1;
    }
}

// ------------------------- stage 5: l2norm + scale + rope ------------------
__global__ void k_qkprep(const float* __restrict__ rope, const float* __restrict__ slog) {
    int i = blockIdx.x, b = blockIdx.y;
    int h = threadIdx.x >> 5, p = threadIdx.x & 31;
    int li = g_idx[b * NR + i];
    const float* base = g_qkv + ((size_t)b * NR + i) * QKVW;
    float2 q = *(const float2*)(base + h * 64 + 2 * p);
    float2 kk = *(const float2*)(base + CC + h * 64 + 2 * p);
    float nq = warpSumF(q.x * q.x + q.y * q.y);
    float nk = warpSumF(kk.x * kk.x + kk.y * kk.y);
    float sm = __expf(fminf(slog[h], 4.6051701859880914f)); // exp(min(., log 100))
    float qs = sm / fmaxf(sqrtf(nq), 1e-12f);
    float ks = 1.f / fmaxf(sqrtf(nk), 1e-12f);
    float cv = rope[(size_t)li * 32 + p];
    float sv = rope[(size_t)LL * 32 + (size_t)li * 32 + p];
    float q0 = q.x * qs, q1 = q.y * qs;
    float k0 = kk.x * ks, k1 = kk.y * ks;
    float2 qr = make_float2(cv * q0 - sv * q1, sv * q0 + cv * q1);
    float2 kr = make_float2(cv * k0 - sv * k1, sv * k0 + cv * k1);
    size_t off = (((size_t)b * NHH + h) * NR + i) * DHH + 2 * p;
    *(float2*)(g_q + off) = qr;
    *(float2*)(g_k + off) = kr;
}

// ------------------------- stage 6: flash attention (fp32) -----------------
#define QW 132
#define KW 68
#define ATTN_SMEM ((64 * QW + 64 * KW + 64 * QW + 64 * KW) * 4)

__global__ void __launch_bounds__(256) k_attn() {
    extern __shared__ float smx[];
    float* Qs = smx;                 // [d][m], 64 x QW
    float* Ks = Qs + 64 * QW;        // [d][c], 64 x KW
    float* Ps = Ks + 64 * KW;        // [c][m], 64 x QW
    float* Vs = Ps + 64 * QW;        // [c][d], 64 x KW
    int tid = threadIdx.x;
    int tx = tid & 15, ty = tid >> 4;
    int qbase = blockIdx.x * 128;
    int h = blockIdx.y, b = blockIdx.z;
    size_t bh = (size_t)(b * NHH + h);
    const float* Qg = g_q + bh * NR * DHH;
    const float* Kg = g_k + bh * NR * DHH;

    // load Q tile (transposed: Qs[d][m])
#pragma unroll
    for (int pass = 0; pass < 8; pass++) {
        int r = pass * 16 + ty;
        int c4 = tx * 4;
        int qi = qbase + r;
        float4 v = make_float4(0.f, 0.f, 0.f, 0.f);
        if (qi < NR) v = *(const float4*)(Qg + (size_t)qi * DHH + c4);
        Qs[(c4 + 0) * QW + r] = v.x; Qs[(c4 + 1) * QW + r] = v.y;
        Qs[(c4 + 2) * QW + r] = v.z; Qs[(c4 + 3) * QW + r] = v.w;
    }

    float mI[8], lI[8], O[8][4];
#pragma unroll
    for (int i = 0; i < 8; i++) {
        mI[i] = -1e30f; lI[i] = 0.f;
#pragma unroll
        for (int j = 0; j < 4; j++) O[i][j] = 0.f;
    }

    for (int kbase = 0; kbase < NR; kbase += 64) {
        int kcount = NR - kbase; if (kcount > 64) kcount = 64;
        __syncthreads(); // prev PV done; Q stores visible on first iter
        {   // load K (transposed) and V (row-major) tiles
            int c = tid >> 2;
            int kc = kbase + c;
            bool ok = (kc < NR);
            const float* krow = Kg + (size_t)kc * DHH;
            const float* vrow = g_qkv + ((size_t)b * NR + kc) * QKVW + 2 * CC + h * 64;
#pragma unroll
            for (int qq = 0; qq < 4; qq++) {
                int d = (tid & 3) * 16 + qq * 4;
                float4 kv = ok ? *(const float4*)(krow + d) : make_float4(0.f, 0.f, 0.f, 0.f);
                Ks[(d + 0) * KW + c] = kv.x; Ks[(d + 1) * KW + c] = kv.y;
                Ks[(d + 2) * KW + c] = kv.z; Ks[(d + 3) * KW + c] = kv.w;
                float4 vv = ok ? *(const float4*)(vrow + d) : make_float4(0.f, 0.f, 0.f, 0.f);
                *(float4*)&Vs[c * KW + d] = vv;
            }
        }
        __syncthreads();

        float s[8][4];
#pragma unroll
        for (int i = 0; i < 8; i++)
#pragma unroll
            for (int j = 0; j < 4; j++) s[i][j] = 0.f;
#pragma unroll 4
        for (int d = 0; d < 64; d++) {
            float4 a0 = *(const float4*)&Qs[d * QW + ty * 8];
            float4 a1 = *(const float4*)&Qs[d * QW + ty * 8 + 4];
            float4 bb = *(const float4*)&Ks[d * KW + tx * 4];
            float av[8] = {a0.x, a0.y, a0.z, a0.w, a1.x, a1.y, a1.z, a1.w};
            float bv[4] = {bb.x, bb.y, bb.z, bb.w};
#pragma unroll
            for (int i = 0; i < 8; i++)
#pragma unroll
                for (int j = 0; j < 4; j++) s[i][j] += av[i] * bv[j];
        }

        // online softmax per row (rows owned by ty-group; reduce over tx half-warp)
#pragma unroll
        for (int i = 0; i < 8; i++) {
            float rm = -1e30f;
#pragma unroll
            for (int j = 0; j < 4; j++) {
                if (tx * 4 + j >= kcount) s[i][j] = -1e30f;
                rm = fmaxf(rm, s[i][j]);
            }
            rm = fmaxf(rm, __shfl_xor_sync(0xffffffffu, rm, 1));
            rm = fmaxf(rm, __shfl_xor_sync(0xffffffffu, rm, 2));
            rm = fmaxf(rm, __shfl_xor_sync(0xffffffffu, rm, 4));
            rm = fmaxf(rm, __shfl_xor_sync(0xffffffffu, rm, 8));
            float mnew = fmaxf(mI[i], rm);
            float corr = __expf(mI[i] - mnew);
            mI[i] = mnew;
            float ls = 0.f;
#pragma unroll
            for (int j = 0; j < 4; j++) {
                float p = __expf(s[i][j] - mnew);
                s[i][j] = p; ls += p;
            }
            ls += __shfl_xor_sync(0xffffffffu, ls, 1);
            ls += __shfl_xor_sync(0xffffffffu, ls, 2);
            ls += __shfl_xor_sync(0xffffffffu, ls, 4);
            ls += __shfl_xor_sync(0xffffffffu, ls, 8);
            lI[i] = lI[i] * corr + ls;
#pragma unroll
            for (int j = 0; j < 4; j++) O[i][j] *= corr;
        }

        // stage P (transposed: Ps[c][m])
#pragma unroll
        for (int i = 0; i < 8; i++)
#pragma unroll
            for (int j = 0; j < 4; j++)
                Ps[(tx * 4 + j) * QW + ty * 8 + i] = s[i][j];
        __syncthreads();

        // O += P @ V
#pragma unroll 4
        for (int c = 0; c < 64; c++) {
            float4 a0 = *(const float4*)&Ps[c * QW + ty * 8];
            float4 a1 = *(const float4*)&Ps[c * QW + ty * 8 + 4];
            float4 bb = *(const float4*)&Vs[c * KW + tx * 4];
            float av[8] = {a0.x, a0.y, a0.z, a0.w, a1.x, a1.y, a1.z, a1.w};
            float bv[4] = {bb.x, bb.y, bb.z, bb.w};
#pragma unroll
            for (int i = 0; i < 8; i++)
#pragma unroll
                for (int j = 0; j < 4; j++) O[i][j] += av[i] * bv[j];
        }
    }

#pragma unroll
    for (int i = 0; i < 8; i++) {
        int qi = qbase + ty * 8 + i;
        if (qi >= NR) continue;
        float inv = 1.f / lI[i];
        float4 o = make_float4(O[i][0] * inv, O[i][1] * inv, O[i][2] * inv, O[i][3] * inv);
        *(float4*)(g_o + ((size_t)b * NR + qi) * CC + h * 64 + tx * 4) = o;
    }
}

// ------------------------- stage 7: residual + upsample + scatter ----------
__global__ void k_out1(const float* __restrict__ x, const float* __restrict__ cached,
                       float* __restrict__ out) {
    size_t e = ((size_t)blockIdx.x * 256 + threadIdx.x) * 4;
    int b = (int)(e >> 22);             // LL*CC = 2^22
    int rem = (int)(e & ((1u << 22) - 1));
    int l = rem >> 10, c = rem & 1023;
    int hh = l >> 6, ww = l & 63;
    size_t uoff = ((((size_t)b * 32 + (hh >> 1)) * 32) + (ww >> 1)) * 1024 + c;
    float4 xv = *(const float4*)(x + e);
    float4 uv = *(const float4*)(cached + uoff);
    *(float4*)(out + e) = make_float4(xv.x + uv.x, xv.y + uv.y, xv.z + uv.z, xv.w + uv.w);
}

__global__ void k_out2(const float* __restrict__ x, float* __restrict__ out) {
    int i = blockIdx.x, b = blockIdx.y;
    int li = g_idx[b * NR + i];
    int c = threadIdx.x * 4;
    size_t xoff = ((size_t)b * LL + li) * CC + c;
    float4 xv = *(const float4*)(x + xoff);
    float4 pv = *(const float4*)(g_pr + ((size_t)b * NR + i) * CC + c);
    *(float4*)(out + xoff) = make_float4(xv.x + pv.x, xv.y + pv.y, xv.z + pv.z, xv.w + pv.w);
}

// ------------------------- launcher ----------------------------------------
extern "C" void kernel_launch(void* const* d_in, const int* in_sizes, int n_in,
                              void* d_out, int out_size) {
    const float* x      = (const float*)d_in[0];
    const float* cached = (const float*)d_in[1];
    const float* Wqkv   = (const float*)d_in[2];
    const float* qb     = (const float*)d_in[3];
    const float* vb     = (const float*)d_in[4];
    const float* Wproj  = (const float*)d_in[5];
    const float* bp     = (const float*)d_in[6];
    const float* slog   = (const float*)d_in[7];
    const float* rope   = (const float*)d_in[8];
    float* out = (float*)d_out;

    void *p_qkv, *p_o, *p_pr, *p_bias;
    cudaGetSymbolAddress(&p_qkv, g_qkv);
    cudaGetSymbolAddress(&p_o, g_o);
    cudaGetSymbolAddress(&p_pr, g_pr);
    cudaGetSymbolAddress(&p_bias, g_bias);

    cudaFuncSetAttribute(k_attn, cudaFuncAttributeMaxDynamicSharedMemorySize, ATTN_SMEM);

    k_colsum<<<dim3(4, 8, BB), 256>>>(x);
    k_meanfin<<<8, 256>>>();
    k_mse<<<dim3(LL, BB), 256>>>(x);
    k_topk<<<BB, 1024>>>();
    k_bias<<<12, 256>>>(qb, vb);
    // QKV projection with gathered rows: (NR x 3072) = x[idx] @ Wqkv^T + bias
    k_gemm<true><<<dim3(24, 13, BB), 256>>>(x, Wqkv, (const float*)p_bias, (float*)p_qkv,
                                            NR, QKVW, (size_t)LL * CC, (size_t)NR * QKVW);
    k_qkprep<<<dim3(NR, BB), 512>>>(rope, slog);
    k_attn<<<dim3(13, NHH, BB), 256, ATTN_SMEM>>>();
    // output projection: (NR x 1024) = o @ Wproj^T + b_proj
    k_gemm<false><<<dim3(8, 13, BB), 256>>>((const float*)p_o, Wproj, bp, (float*)p_pr,
                                            NR, CC, (size_t)NR * CC, (size_t)NR * CC);
    k_out1<<<8192, 256>>>(x, cached, out);
    k_out2<<<dim3(NR, BB), 256>>>(x, out);
}

// round 6
// speedup vs baseline: 1.2478x; 1.2478x over previous
#include <cuda_runtime.h>
#include <cuda_bf16.h>
#include <math.h>
#include <stdint.h>

#define BB 2
#define LL 4096
#define CC 1024
#define NHH 16
#define DHH 64
#define NR 1638
#define QKVW 3072
#define GK 3072          // packed split-K (3 x 1024)

// ------------------------- scratch (device globals; no runtime alloc) -------
__device__ float g_mean[BB * CC];
__device__ double g_part[BB * 8 * CC];
__device__ float g_mse[BB * LL];
__device__ int g_idx[BB * NR];
__device__ float g_bias[QKVW];
__device__ float g_qkv[(size_t)BB * NR * QKVW];   // (b, i, 3*C)
__device__ float g_q[(size_t)BB * NHH * NR * DHH];
__device__ float g_k[(size_t)BB * NHH * NR * DHH];
__device__ float g_o[(size_t)BB * NR * CC];
__device__ float g_pr[(size_t)BB * NR * CC];
// bf16 split-packed operands
__device__ __nv_bfloat16 g_ax[(size_t)BB * NR * GK];   // x[idx] split  [hi|hi|lo]
__device__ __nv_bfloat16 g_wq[(size_t)QKVW * GK];      // Wqkv split   [hi|lo|hi]
__device__ __nv_bfloat16 g_wp[(size_t)CC * GK];        // Wproj split  [hi|lo|hi]
__device__ __nv_bfloat16 g_ao[(size_t)BB * NR * GK];   // attn out split [hi|hi|lo]

// ------------------------- helpers -----------------------------------------
__device__ __forceinline__ float warpSumF(float v) {
#pragma unroll
    for (int m = 16; m; m >>= 1) v += __shfl_xor_sync(0xffffffffu, v, m);
    return v;
}
__device__ __forceinline__ double warpSumD(double v) {
#pragma unroll
    for (int m = 16; m; m >>= 1) v += __shfl_xor_sync(0xffffffffu, v, m);
    return v;
}
__device__ __forceinline__ uint32_t s2u(const void* p) {
    uint32_t a;
    asm("{ .reg .u64 t; cvta.to.shared.u64 t, %1; cvt.u32.u64 %0, t; }" : "=r"(a) : "l"(p));
    return a;
}
#define LDSM4(d0, d1, d2, d3, addr) \
    asm volatile("ldmatrix.sync.aligned.m8n8.x4.shared.b16 {%0,%1,%2,%3}, [%4];" \
                 : "=r"(d0), "=r"(d1), "=r"(d2), "=r"(d3) : "r"(addr))
#define LDSM2(d0, d1, addr) \
    asm volatile("ldmatrix.sync.aligned.m8n8.x2.shared.b16 {%0,%1}, [%2];" \
                 : "=r"(d0), "=r"(d1) : "r"(addr))
#define MMA16816(c0, c1, c2, c3, a0, a1, a2, a3, b0, b1) \
    asm volatile("mma.sync.aligned.m16n8k16.row.col.f32.bf16.bf16.f32 " \
                 "{%0,%1,%2,%3}, {%4,%5,%6,%7}, {%8,%9}, {%0,%1,%2,%3};" \
                 : "+f"(c0), "+f"(c1), "+f"(c2), "+f"(c3) \
                 : "r"(a0), "r"(a1), "r"(a2), "r"(a3), "r"(b0), "r"(b1))

// ------------------------- stage 1: mean over L (fp64 accum) ---------------
__global__ void k_colsum(const float* __restrict__ x) {
    int c = blockIdx.x * 256 + threadIdx.x;
    int b = blockIdx.z;
    int l0 = blockIdx.y * 512;
    const float* p = x + ((size_t)b * LL + l0) * CC + c;
    double a0 = 0, a1 = 0, a2 = 0, a3 = 0;
#pragma unroll 4
    for (int l = 0; l < 512; l += 4) {
        a0 += (double)p[(size_t)(l + 0) * CC];
        a1 += (double)p[(size_t)(l + 1) * CC];
        a2 += (double)p[(size_t)(l + 2) * CC];
        a3 += (double)p[(size_t)(l + 3) * CC];
    }
    g_part[(b * 8 + blockIdx.y) * CC + c] = a0 + a1 + a2 + a3;
}

__global__ void k_meanfin() {
    int i = blockIdx.x * 256 + threadIdx.x;
    int b = i >> 10, c = i & 1023;
    double s = 0;
#pragma unroll
    for (int k = 0; k < 8; k++) s += g_part[(b * 8 + k) * CC + c];
    g_mean[b * CC + c] = (float)(s * (1.0 / (double)LL));
}

// ------------------------- stage 2: per-row mse (fp64 accum) ---------------
__global__ void k_mse(const float* __restrict__ x) {
    int l = blockIdx.x, b = blockIdx.y;
    const float* xr = x + ((size_t)b * LL + l) * CC;
    double acc = 0;
#pragma unroll
    for (int k = 0; k < 4; k++) {
        int c = threadIdx.x + k * 256;
        double d = (double)xr[c] - (double)g_mean[b * CC + c];
        acc += d * d;
    }
    acc = warpSumD(acc);
    __shared__ double red[8];
    if ((threadIdx.x & 31) == 0) red[threadIdx.x >> 5] = acc;
    __syncthreads();
    if (threadIdx.x == 0) {
        double t = 0;
#pragma unroll
        for (int w = 0; w < 8; w++) t += red[w];
        g_mse[b * LL + l] = (float)t;
    }
}

// ------------------------- stage 3: top-NR selection (bitonic) -------------
__global__ void k_topk() {
    __shared__ unsigned long long keys[LL];
    int b = blockIdx.x;
    for (int i = threadIdx.x; i < LL; i += blockDim.x) {
        unsigned int fb = __float_as_uint(g_mse[b * LL + i]);
        keys[i] = ((unsigned long long)fb << 32) | (unsigned int)i;
    }
    __syncthreads();
    for (int k = 2; k <= LL; k <<= 1) {
        for (int j = k >> 1; j > 0; j >>= 1) {
            for (int t = threadIdx.x; t < LL / 2; t += blockDim.x) {
                int i = (t / j) * (2 * j) + (t % j);
                int ixj = i ^ j;
                bool up = ((i & k) == 0);
                unsigned long long a = keys[i], c = keys[ixj];
                bool sw = up ? (a < c) : (a > c);
                if (sw) { keys[i] = c; keys[ixj] = a; }
            }
            __syncthreads();
        }
    }
    for (int i = threadIdx.x; i < NR; i += blockDim.x)
        g_idx[b * NR + i] = (int)(keys[i] & 0xFFFFFFFFu);
}

// ------------------------- stage 4: fused bias ------------------------------
__global__ void k_bias(const float* __restrict__ qb, const float* __restrict__ vb) {
    int i = blockIdx.x * 256 + threadIdx.x;
    if (i < QKVW) g_bias[i] = (i < CC) ? qb[i] : ((i < 2 * CC) ? 0.f : vb[i - 2 * CC]);
}

// ------------------------- split/pack kernels -------------------------------
__global__ void k_splitB(const float* __restrict__ W, __nv_bfloat16* __restrict__ out, int total) {
    int i = blockIdx.x * 256 + threadIdx.x;
    if (i >= total) return;
    int r = i >> 10, c = i & 1023;
    float v = W[i];
    __nv_bfloat16 h = __float2bfloat16(v);
    __nv_bfloat16 l = __float2bfloat16(v - __bfloat162float(h));
    size_t o = (size_t)r * GK;
    out[o + c] = h;
    out[o + 1024 + c] = l;
    out[o + 2048 + c] = h;
}
__global__ void k_splitAx(const float* __restrict__ x, __nv_bfloat16* __restrict__ out) {
    int i = blockIdx.x * 256 + threadIdx.x;
    if (i >= BB * NR * CC) return;
    int c = i & 1023;
    int t = i >> 10;
    int r = t % NR, b = t / NR;
    int li = g_idx[b * NR + r];
    float v = x[((size_t)b * LL + li) * CC + c];
    __nv_bfloat16 h = __float2bfloat16(v);
    __nv_bfloat16 l = __float2bfloat16(v - __bfloat162float(h));
    size_t o = (size_t)t * GK;
    out[o + c] = h;
    out[o + 1024 + c] = h;
    out[o + 2048 + c] = l;
}
__global__ void k_splitAo(const float* __restrict__ src, __nv_bfloat16* __restrict__ out) {
    int i = blockIdx.x * 256 + threadIdx.x;
    if (i >= BB * NR * CC) return;
    int c = i & 1023;
    int t = i >> 10;
    float v = src[i];
    __nv_bfloat16 h = __float2bfloat16(v);
    __nv_bfloat16 l = __float2bfloat16(v - __bfloat162float(h));
    size_t o = (size_t)t * GK;
    out[o + c] = h;
    out[o + 1024 + c] = h;
    out[o + 2048 + c] = l;
}

// ------------------------- tensor GEMM via mma.sync bf16 -------------------
// C(M,N) = A(M,GK) @ B(N,GK)^T + bias.  BM=128 BN=128 BK=32, 8 warps.
#define PITCH 40          // bf16 elems per smem row (32 data + 8 pad)
#define KITERS (GK / 32)  // 96

__global__ void __launch_bounds__(256, 2) k_mgemm(
    const __nv_bfloat16* __restrict__ A, const __nv_bfloat16* __restrict__ Bm,
    const float* __restrict__ bias, float* __restrict__ C,
    int M, int N, size_t aBatch, size_t cBatch)
{
    __shared__ __nv_bfloat16 Asm[2][128 * PITCH];
    __shared__ __nv_bfloat16 Bsm[2][128 * PITCH];

    int tid = threadIdx.x, wid = tid >> 5, lane = tid & 31;
    int bm = blockIdx.y * 128, bn = blockIdx.x * 128, b = blockIdx.z;
    int wm = wid >> 2, wn = wid & 3;     // 2 x 4 warp grid; warp tile 64 x 32
    const __nv_bfloat16* Ab = A + (size_t)b * aBatch;

    // loader mapping: row = tid>>1 (0..127), col halves of 16 elems
    int lr = tid >> 1, lc = (tid & 1) * 16;
    bool aok = (bm + lr < M);
    const uint4* aG = (const uint4*)(Ab + (size_t)(aok ? bm + lr : 0) * GK + lc);
    const uint4* bG = (const uint4*)(Bm + (size_t)(bn + lr) * GK + lc);
    uint32_t aS = s2u(&Asm[0][0]) + (lr * PITCH + lc) * 2;
    uint32_t bS = s2u(&Bsm[0][0]) + (lr * PITCH + lc) * 2;
    const uint32_t BUF = 128 * PITCH * 2;   // bytes per buffer

    // ldmatrix source addresses for this lane
    uint32_t aL = s2u(&Asm[0][0]) +
                  ((wm * 64 + (lane & 15)) * PITCH + (lane >> 4) * 8) * 2;
    uint32_t bL = s2u(&Bsm[0][0]) +
                  ((wn * 32 + (lane & 7)) * PITCH + ((lane >> 3) & 1) * 8) * 2;

    float acc[4][4][4];
#pragma unroll
    for (int i = 0; i < 4; i++)
#pragma unroll
        for (int j = 0; j < 4; j++)
#pragma unroll
            for (int r = 0; r < 4; r++) acc[i][j][r] = 0.f;

    // prologue: stage k-chunk 0 into buffer 0
    {
        uint4 a0 = aok ? aG[0] : make_uint4(0, 0, 0, 0);
        uint4 a1 = aok ? aG[1] : make_uint4(0, 0, 0, 0);
        uint4 b0 = bG[0], b1 = bG[1];
        *(uint4*)(Asm[0] + lr * PITCH + lc) = a0;
        *(uint4*)(Asm[0] + lr * PITCH + lc + 8) = a1;
        *(uint4*)(Bsm[0] + lr * PITCH + lc) = b0;
        *(uint4*)(Bsm[0] + lr * PITCH + lc + 8) = b1;
    }
    __syncthreads();

    for (int kt = 0; kt < KITERS; kt++) {
        int s = kt & 1;
        uint4 na0, na1, nb0, nb1;
        bool more = (kt + 1 < KITERS);
        if (more) {
            const uint4* ag = (const uint4*)((const __nv_bfloat16*)aG + (kt + 1) * 32);
            const uint4* bg = (const uint4*)((const __nv_bfloat16*)bG + (kt + 1) * 32);
            na0 = aok ? ag[0] : make_uint4(0, 0, 0, 0);
            na1 = aok ? ag[1] : make_uint4(0, 0, 0, 0);
            nb0 = bg[0]; nb1 = bg[1];
        }

        uint32_t aBase = aL + s * BUF, bBase = bL + s * BUF;
#pragma unroll
        for (int k16 = 0; k16 < 2; k16++) {
            uint32_t af[4][4], bf[4][2];
#pragma unroll
            for (int i = 0; i < 4; i++)
                LDSM4(af[i][0], af[i][1], af[i][2], af[i][3],
                      aBase + (i * 16 * PITCH + k16 * 16) * 2);
#pragma unroll
            for (int j = 0; j < 4; j++)
                LDSM2(bf[j][0], bf[j][1],
                      bBase + (j * 8 * PITCH + k16 * 16) * 2);
#pragma unroll
            for (int i = 0; i < 4; i++)
#pragma unroll
                for (int j = 0; j < 4; j++)
                    MMA16816(acc[i][j][0], acc[i][j][1], acc[i][j][2], acc[i][j][3],
                             af[i][0], af[i][1], af[i][2], af[i][3],
                             bf[j][0], bf[j][1]);
        }

        if (more) {
            int d = s ^ 1;
            *(uint4*)((char*)(Asm[0] + lr * PITCH + lc) + d * BUF) = na0;
            *(uint4*)((char*)(Asm[0] + lr * PITCH + lc + 8) + d * BUF) = na1;
            *(uint4*)((char*)(Bsm[0] + lr * PITCH + lc) + d * BUF) = nb0;
            *(uint4*)((char*)(Bsm[0] + lr * PITCH + lc + 8) + d * BUF) = nb1;
        }
        __syncthreads();
    }

    // epilogue: thread t in mma tile holds rows (t/4, t/4+8), cols (t%4)*2,+1
    float* Cb = C + (size_t)b * cBatch;
    int rq = lane >> 2, cq = (lane & 3) * 2;
#pragma unroll
    for (int i = 0; i < 4; i++) {
#pragma unroll
        for (int j = 0; j < 4; j++) {
            int col = bn + wn * 32 + j * 8 + cq;
            float b0 = bias[col], b1 = bias[col + 1];
            int r0 = bm + wm * 64 + i * 16 + rq;
            if (r0 < M) {
                float2 v = make_float2(acc[i][j][0] + b0, acc[i][j][1] + b1);
                *(float2*)(Cb + (size_t)r0 * N + col) = v;
            }
            if (r0 + 8 < M) {
                float2 v = make_float2(acc[i][j][2] + b0, acc[i][j][3] + b1);
                *(float2*)(Cb + (size_t)(r0 + 8) * N + col) = v;
            }
        }
    }
}

// ------------------------- stage 5: l2norm + scale + rope ------------------
__global__ void k_qkprep(const float* __restrict__ rope, const float* __restrict__ slog) {
    int i = blockIdx.x, b = blockIdx.y;
    int h = threadIdx.x >> 5, p = threadIdx.x & 31;
    int li = g_idx[b * NR + i];
    const float* base = g_qkv + ((size_t)b * NR + i) * QKVW;
    float2 q = *(const float2*)(base + h * 64 + 2 * p);
    float2 kk = *(const float2*)(base + CC + h * 64 + 2 * p);
    float nq = warpSumF(q.x * q.x + q.y * q.y);
    float nk = warpSumF(kk.x * kk.x + kk.y * kk.y);
    float sm = __expf(fminf(slog[h], 4.6051701859880914f));
    float qs = sm / fmaxf(sqrtf(nq), 1e-12f);
    float ks = 1.f / fmaxf(sqrtf(nk), 1e-12f);
    float cv = rope[(size_t)li * 32 + p];
    float sv = rope[(size_t)LL * 32 + (size_t)li * 32 + p];
    float q0 = q.x * qs, q1 = q.y * qs;
    float k0 = kk.x * ks, k1 = kk.y * ks;
    float2 qr = make_float2(cv * q0 - sv * q1, sv * q0 + cv * q1);
    float2 kr = make_float2(cv * k0 - sv * k1, sv * k0 + cv * k1);
    size_t off = (((size_t)b * NHH + h) * NR + i) * DHH + 2 * p;
    *(float2*)(g_q + off) = qr;
    *(float2*)(g_k + off) = kr;
}

// ------------------------- stage 6: flash attention (fp32 SIMT) ------------
#define QW 132
#define KW 68
#define ATTN_SMEM ((64 * QW + 64 * KW + 64 * QW + 64 * KW) * 4)

__global__ void __launch_bounds__(256) k_attn() {
    extern __shared__ float smx[];
    float* Qs = smx;
    float* Ks = Qs + 64 * QW;
    float* Ps = Ks + 64 * KW;
    float* Vs = Ps + 64 * QW;
    int tid = threadIdx.x;
    int tx = tid & 15, ty = tid >> 4;
    int qbase = blockIdx.x * 128;
    int h = blockIdx.y, b = blockIdx.z;
    size_t bh = (size_t)(b * NHH + h);
    const float* Qg = g_q + bh * NR * DHH;
    const float* Kg = g_k + bh * NR * DHH;

#pragma unroll
    for (int pass = 0; pass < 8; pass++) {
        int r = pass * 16 + ty;
        int c4 = tx * 4;
        int qi = qbase + r;
        float4 v = make_float4(0.f, 0.f, 0.f, 0.f);
        if (qi < NR) v = *(const float4*)(Qg + (size_t)qi * DHH + c4);
        Qs[(c4 + 0) * QW + r] = v.x; Qs[(c4 + 1) * QW + r] = v.y;
        Qs[(c4 + 2) * QW + r] = v.z; Qs[(c4 + 3) * QW + r] = v.w;
    }

    float mI[8], lI[8], O[8][4];
#pragma unroll
    for (int i = 0; i < 8; i++) {
        mI[i] = -1e30f; lI[i] = 0.f;
#pragma unroll
        for (int j = 0; j < 4; j++) O[i][j] = 0.f;
    }

    for (int kbase = 0; kbase < NR; kbase += 64) {
        int kcount = NR - kbase; if (kcount > 64) kcount = 64;
        __syncthreads();
        {
            int c = tid >> 2;
            int kc = kbase + c;
            bool ok = (kc < NR);
            const float* krow = Kg + (size_t)kc * DHH;
            const float* vrow = g_qkv + ((size_t)b * NR + kc) * QKVW + 2 * CC + h * 64;
#pragma unroll
            for (int qq = 0; qq < 4; qq++) {
                int d = (tid & 3) * 16 + qq * 4;
                float4 kv = ok ? *(const float4*)(krow + d) : make_float4(0.f, 0.f, 0.f, 0.f);
                Ks[(d + 0) * KW + c] = kv.x; Ks[(d + 1) * KW + c] = kv.y;
                Ks[(d + 2) * KW + c] = kv.z; Ks[(d + 3) * KW + c] = kv.w;
                float4 vv = ok ? *(const float4*)(vrow + d) : make_float4(0.f, 0.f, 0.f, 0.f);
                *(float4*)&Vs[c * KW + d] = vv;
            }
        }
        __syncthreads();

        float s[8][4];
#pragma unroll
        for (int i = 0; i < 8; i++)
#pragma unroll
            for (int j = 0; j < 4; j++) s[i][j] = 0.f;
#pragma unroll 4
        for (int d = 0; d < 64; d++) {
            float4 a0 = *(const float4*)&Qs[d * QW + ty * 8];
            float4 a1 = *(const float4*)&Qs[d * QW + ty * 8 + 4];
            float4 bb = *(const float4*)&Ks[d * KW + tx * 4];
            float av[8] = {a0.x, a0.y, a0.z, a0.w, a1.x, a1.y, a1.z, a1.w};
            float bv[4] = {bb.x, bb.y, bb.z, bb.w};
#pragma unroll
            for (int i = 0; i < 8; i++)
#pragma unroll
                for (int j = 0; j < 4; j++) s[i][j] += av[i] * bv[j];
        }

#pragma unroll
        for (int i = 0; i < 8; i++) {
            float rm = -1e30f;
#pragma unroll
            for (int j = 0; j < 4; j++) {
                if (tx * 4 + j >= kcount) s[i][j] = -1e30f;
                rm = fmaxf(rm, s[i][j]);
            }
            rm = fmaxf(rm, __shfl_xor_sync(0xffffffffu, rm, 1));
            rm = fmaxf(rm, __shfl_xor_sync(0xffffffffu, rm, 2));
            rm = fmaxf(rm, __shfl_xor_sync(0xffffffffu, rm, 4));
            rm = fmaxf(rm, __shfl_xor_sync(0xffffffffu, rm, 8));
            float mnew = fmaxf(mI[i], rm);
            float corr = __expf(mI[i] - mnew);
            mI[i] = mnew;
            float ls = 0.f;
#pragma unroll
            for (int j = 0; j < 4; j++) {
                float p = __expf(s[i][j] - mnew);
                s[i][j] = p; ls += p;
            }
            ls += __shfl_xor_sync(0xffffffffu, ls, 1);
            ls += __shfl_xor_sync(0xffffffffu, ls, 2);
            ls += __shfl_xor_sync(0xffffffffu, ls, 4);
            ls += __shfl_xor_sync(0xffffffffu, ls, 8);
            lI[i] = lI[i] * corr + ls;
#pragma unroll
            for (int j = 0; j < 4; j++) O[i][j] *= corr;
        }

#pragma unroll
        for (int i = 0; i < 8; i++)
#pragma unroll
            for (int j = 0; j < 4; j++)
                Ps[(tx * 4 + j) * QW + ty * 8 + i] = s[i][j];
        __syncthreads();

#pragma unroll 4
        for (int c = 0; c < 64; c++) {
            float4 a0 = *(const float4*)&Ps[c * QW + ty * 8];
            float4 a1 = *(const float4*)&Ps[c * QW + ty * 8 + 4];
            float4 bb = *(const float4*)&Vs[c * KW + tx * 4];
            float av[8] = {a0.x, a0.y, a0.z, a0.w, a1.x, a1.y, a1.z, a1.w};
            float bv[4] = {bb.x, bb.y, bb.z, bb.w};
#pragma unroll
            for (int i = 0; i < 8; i++)
#pragma unroll
                for (int j = 0; j < 4; j++) O[i][j] += av[i] * bv[j];
        }
    }

#pragma unroll
    for (int i = 0; i < 8; i++) {
        int qi = qbase + ty * 8 + i;
        if (qi >= NR) continue;
        float inv = 1.f / lI[i];
        float4 o = make_float4(O[i][0] * inv, O[i][1] * inv, O[i][2] * inv, O[i][3] * inv);
        *(float4*)(g_o + ((size_t)b * NR + qi) * CC + h * 64 + tx * 4) = o;
    }
}

// ------------------------- stage 7: residual + upsample + scatter ----------
__global__ void k_out1(const float* __restrict__ x, const float* __restrict__ cached,
                       float* __restrict__ out) {
    size_t e = ((size_t)blockIdx.x * 256 + threadIdx.x) * 4;
    int b = (int)(e >> 22);
    int rem = (int)(e & ((1u << 22) - 1));
    int l = rem >> 10, c = rem & 1023;
    int hh = l >> 6, ww = l & 63;
    size_t uoff = ((((size_t)b * 32 + (hh >> 1)) * 32) + (ww >> 1)) * 1024 + c;
    float4 xv = *(const float4*)(x + e);
    float4 uv = *(const float4*)(cached + uoff);
    *(float4*)(out + e) = make_float4(xv.x + uv.x, xv.y + uv.y, xv.z + uv.z, xv.w + uv.w);
}

__global__ void k_out2(const float* __restrict__ x, float* __restrict__ out) {
    int i = blockIdx.x, b = blockIdx.y;
    int li = g_idx[b * NR + i];
    int c = threadIdx.x * 4;
    size_t xoff = ((size_t)b * LL + li) * CC + c;
    float4 xv = *(const float4*)(x + xoff);
    float4 pv = *(const float4*)(g_pr + ((size_t)b * NR + i) * CC + c);
    *(float4*)(out + xoff) = make_float4(xv.x + pv.x, xv.y + pv.y, xv.z + pv.z, xv.w + pv.w);
}

// ------------------------- launcher ----------------------------------------
extern "C" void kernel_launch(void* const* d_in, const int* in_sizes, int n_in,
                              void* d_out, int out_size) {
    const float* x      = (const float*)d_in[0];
    const float* cached = (const float*)d_in[1];
    const float* Wqkv   = (const float*)d_in[2];
    const float* qb     = (const float*)d_in[3];
    const float* vb     = (const float*)d_in[4];
    const float* Wproj  = (const float*)d_in[5];
    const float* bp     = (const float*)d_in[6];
    const float* slog   = (const float*)d_in[7];
    const float* rope   = (const float*)d_in[8];
    float* out = (float*)d_out;

    void *p_qkv, *p_o, *p_pr, *p_bias, *p_ax, *p_wq, *p_wp, *p_ao;
    cudaGetSymbolAddress(&p_qkv, g_qkv);
    cudaGetSymbolAddress(&p_o, g_o);
    cudaGetSymbolAddress(&p_pr, g_pr);
    cudaGetSymbolAddress(&p_bias, g_bias);
    cudaGetSymbolAddress(&p_ax, g_ax);
    cudaGetSymbolAddress(&p_wq, g_wq);
    cudaGetSymbolAddress(&p_wp, g_wp);
    cudaGetSymbolAddress(&p_ao, g_ao);

    cudaFuncSetAttribute(k_attn, cudaFuncAttributeMaxDynamicSharedMemorySize, ATTN_SMEM);

    k_colsum<<<dim3(4, 8, BB), 256>>>(x);
    k_meanfin<<<8, 256>>>();
    k_mse<<<dim3(LL, BB), 256>>>(x);
    k_topk<<<BB, 1024>>>();
    k_bias<<<12, 256>>>(qb, vb);

    // pack split-bf16 operands
    k_splitB<<<(QKVW * CC + 255) / 256, 256>>>(Wqkv, (__nv_bfloat16*)p_wq, QKVW * CC);
    k_splitB<<<(CC * CC + 255) / 256, 256>>>(Wproj, (__nv_bfloat16*)p_wp, CC * CC);
    k_splitAx<<<(BB * NR * CC + 255) / 256, 256>>>(x, (__nv_bfloat16*)p_ax);

    // QKV projection (tensor): (NR x 3072) = split(x[idx]) @ split(Wqkv)^T + bias
    k_mgemm<<<dim3(QKVW / 128, 13, BB), 256>>>(
        (const __nv_bfloat16*)p_ax, (const __nv_bfloat16*)p_wq,
        (const float*)p_bias, (float*)p_qkv,
        NR, QKVW, (size_t)NR * GK, (size_t)NR * QKVW);

    k_qkprep<<<dim3(NR, BB), 512>>>(rope, slog);
    k_attn<<<dim3(13, NHH, BB), 256, ATTN_SMEM>>>();

    // output projection (tensor): (NR x 1024) = split(o) @ split(Wproj)^T + b_proj
    k_splitAo<<<(BB * NR * CC + 255) / 256, 256>>>((const float*)p_o, (__nv_bfloat16*)p_ao);
    k_mgemm<<<dim3(CC / 128, 13, BB), 256>>>(
        (const __nv_bfloat16*)p_ao, (const __nv_bfloat16*)p_wp,
        bp, (float*)p_pr,
        NR, CC, (size_t)NR * GK, (size_t)NR * CC);

    k_out1<<<8192, 256>>>(x, cached, out);
    k_out2<<<dim3(NR, BB), 256>>>(x, out);
}

// round 8
// speedup vs baseline: 1.3278x; 1.0641x over previous
#include <cuda_runtime.h>
#include <cuda_bf16.h>
#include <math.h>
#include <stdint.h>

#define BB 2
#define LL 4096
#define CC 1024
#define NHH 16
#define DHH 64
#define NR 1638
#define QKVW 3072
#define GK 3072          // packed split-K (3 x 1024)

// ------------------------- scratch (device globals; no runtime alloc) -------
__device__ float g_mean[BB * CC];
__device__ double g_part[BB * 8 * CC];
__device__ float g_mse[BB * LL];
__device__ int g_idx[BB * NR];
__device__ float g_bias[QKVW];
__device__ float g_qkv[(size_t)BB * NR * QKVW];   // (b, i, 3*C)
__device__ float g_o[(size_t)BB * NR * CC];
__device__ float g_pr[(size_t)BB * NR * CC];
// bf16 attention operands
__device__ __nv_bfloat16 g_qb[(size_t)BB * NHH * NR * DHH];
__device__ __nv_bfloat16 g_kb[(size_t)BB * NHH * NR * DHH];
__device__ __nv_bfloat16 g_vb[(size_t)BB * NR * CC];
// bf16 split-packed GEMM operands
__device__ __nv_bfloat16 g_ax[(size_t)BB * NR * GK];   // x[idx] split  [hi|hi|lo]
__device__ __nv_bfloat16 g_wq[(size_t)QKVW * GK];      // Wqkv split   [hi|lo|hi]
__device__ __nv_bfloat16 g_wp[(size_t)CC * GK];        // Wproj split  [hi|lo|hi]
__device__ __nv_bfloat16 g_ao[(size_t)BB * NR * GK];   // attn out split [hi|hi|lo]

// ------------------------- helpers -----------------------------------------
__device__ __forceinline__ float warpSumF(float v) {
#pragma unroll
    for (int m = 16; m; m >>= 1) v += __shfl_xor_sync(0xffffffffu, v, m);
    return v;
}
__device__ __forceinline__ double warpSumD(double v) {
#pragma unroll
    for (int m = 16; m; m >>= 1) v += __shfl_xor_sync(0xffffffffu, v, m);
    return v;
}
__device__ __forceinline__ uint32_t s2u(const void* p) {
    uint32_t a;
    asm("{ .reg .u64 t; cvta.to.shared.u64 t, %1; cvt.u32.u64 %0, t; }" : "=r"(a) : "l"(p));
    return a;
}
__device__ __forceinline__ uint32_t packbf(float a, float b) {
    __nv_bfloat162 t = __floats2bfloat162_rn(a, b);   // x=a (low), y=b (high)
    return *(uint32_t*)&t;
}
#define LDSM4(d0, d1, d2, d3, addr) \
    asm volatile("ldmatrix.sync.aligned.m8n8.x4.shared.b16 {%0,%1,%2,%3}, [%4];" \
                 : "=r"(d0), "=r"(d1), "=r"(d2), "=r"(d3) : "r"(addr))
#define LDSM2(d0, d1, addr) \
    asm volatile("ldmatrix.sync.aligned.m8n8.x2.shared.b16 {%0,%1}, [%2];" \
                 : "=r"(d0), "=r"(d1) : "r"(addr))
#define LDSM2T(d0, d1, addr) \
    asm volatile("ldmatrix.sync.aligned.m8n8.x2.trans.shared.b16 {%0,%1}, [%2];" \
                 : "=r"(d0), "=r"(d1) : "r"(addr))
#define MMA16816(c0, c1, c2, c3, a0, a1, a2, a3, b0, b1) \
    asm volatile("mma.sync.aligned.m16n8k16.row.col.f32.bf16.bf16.f32 " \
                 "{%0,%1,%2,%3}, {%4,%5,%6,%7}, {%8,%9}, {%0,%1,%2,%3};" \
                 : "+f"(c0), "+f"(c1), "+f"(c2), "+f"(c3) \
                 : "r"(a0), "r"(a1), "r"(a2), "r"(a3), "r"(b0), "r"(b1))

// ------------------------- stage 1: mean over L (fp64 accum) ---------------
__global__ void k_colsum(const float* __restrict__ x) {
    int c = blockIdx.x * 256 + threadIdx.x;
    int b = blockIdx.z;
    int l0 = blockIdx.y * 512;
    const float* p = x + ((size_t)b * LL + l0) * CC + c;
    double a0 = 0, a1 = 0, a2 = 0, a3 = 0;
#pragma unroll 4
    for (int l = 0; l < 512; l += 4) {
        a0 += (double)p[(size_t)(l + 0) * CC];
        a1 += (double)p[(size_t)(l + 1) * CC];
        a2 += (double)p[(size_t)(l + 2) * CC];
        a3 += (double)p[(size_t)(l + 3) * CC];
    }
    g_part[(b * 8 + blockIdx.y) * CC + c] = a0 + a1 + a2 + a3;
}

__global__ void k_meanfin() {
    int i = blockIdx.x * 256 + threadIdx.x;
    int b = i >> 10, c = i & 1023;
    double s = 0;
#pragma unroll
    for (int k = 0; k < 8; k++) s += g_part[(b * 8 + k) * CC + c];
    g_mean[b * CC + c] = (float)(s * (1.0 / (double)LL));
}

// ------------------------- stage 2: per-row mse (fp64 accum) ---------------
__global__ void k_mse(const float* __restrict__ x) {
    int l = blockIdx.x, b = blockIdx.y;
    const float* xr = x + ((size_t)b * LL + l) * CC;
    double acc = 0;
#pragma unroll
    for (int k = 0; k < 4; k++) {
        int c = threadIdx.x + k * 256;
        double d = (double)xr[c] - (double)g_mean[b * CC + c];
        acc += d * d;
    }
    acc = warpSumD(acc);
    __shared__ double red[8];
    if ((threadIdx.x & 31) == 0) red[threadIdx.x >> 5] = acc;
    __syncthreads();
    if (threadIdx.x == 0) {
        double t = 0;
#pragma unroll
        for (int w = 0; w < 8; w++) t += red[w];
        g_mse[b * LL + l] = (float)t;
    }
}

// ------------------------- stage 3: top-NR via 4-pass radix select ---------
__global__ void k_topk() {
    __shared__ unsigned int hist[256];
    __shared__ unsigned int sh_pref, sh_rank, sh_cgt, sh_ceq;
    int b = blockIdx.x, tid = threadIdx.x;   // 1024 threads
    unsigned int key[4];
#pragma unroll
    for (int k = 0; k < 4; k++)
        key[k] = __float_as_uint(g_mse[b * LL + tid * 4 + k]);  // mse>=0: monotonic bits
    if (tid == 0) { sh_pref = 0; sh_rank = NR; }
#pragma unroll
    for (int pass = 0; pass < 4; pass++) {
        int shift = 24 - pass * 8;
        if (tid < 256) hist[tid] = 0;
        __syncthreads();
        unsigned int pref = sh_pref;
        unsigned int himask = (pass == 0) ? 0u : (0xFFFFFFFFu << (shift + 8));
#pragma unroll
        for (int k = 0; k < 4; k++)
            if ((key[k] & himask) == pref)
                atomicAdd(&hist[(key[k] >> shift) & 255], 1u);
        __syncthreads();
        if (tid == 0) {
            unsigned int r = sh_rank, cum = 0;
            int bin = 255;
            for (; bin > 0; bin--) {
                if (cum + hist[bin] >= r) break;
                cum += hist[bin];
            }
            sh_pref = pref | ((unsigned int)bin << shift);
            sh_rank = r - cum;
        }
        __syncthreads();
    }
    if (tid == 0) { sh_cgt = 0; sh_ceq = 0; }
    __syncthreads();
    unsigned int thr = sh_pref, need = sh_rank;
    int ngt = NR - (int)need;
#pragma unroll
    for (int k = 0; k < 4; k++) {
        if (key[k] > thr) {
            unsigned int p = atomicAdd(&sh_cgt, 1u);
            g_idx[b * NR + p] = tid * 4 + k;
        } else if (key[k] == thr) {
            unsigned int p = atomicAdd(&sh_ceq, 1u);
            if (p < need) g_idx[b * NR + ngt + p] = tid * 4 + k;
        }
    }
}

// ------------------------- stage 4: fused bias ------------------------------
__global__ void k_bias(const float* __restrict__ qb, const float* __restrict__ vb) {
    int i = blockIdx.x * 256 + threadIdx.x;
    if (i < QKVW) g_bias[i] = (i < CC) ? qb[i] : ((i < 2 * CC) ? 0.f : vb[i - 2 * CC]);
}

// ------------------------- split/pack kernels -------------------------------
__global__ void k_splitB(const float* __restrict__ W, __nv_bfloat16* __restrict__ out, int total) {
    int i = blockIdx.x * 256 + threadIdx.x;
    if (i >= total) return;
    int r = i >> 10, c = i & 1023;
    float v = W[i];
    __nv_bfloat16 h = __float2bfloat16(v);
    __nv_bfloat16 l = __float2bfloat16(v - __bfloat162float(h));
    size_t o = (size_t)r * GK;
    out[o + c] = h;
    out[o + 1024 + c] = l;
    out[o + 2048 + c] = h;
}
__global__ void k_splitAx(const float* __restrict__ x, __nv_bfloat16* __restrict__ out) {
    int i = blockIdx.x * 256 + threadIdx.x;
    if (i >= BB * NR * CC) return;
    int c = i & 1023;
    int t = i >> 10;
    int r = t % NR, b = t / NR;
    int li = g_idx[b * NR + r];
    float v = x[((size_t)b * LL + li) * CC + c];
    __nv_bfloat16 h = __float2bfloat16(v);
    __nv_bfloat16 l = __float2bfloat16(v - __bfloat162float(h));
    size_t o = (size_t)t * GK;
    out[o + c] = h;
    out[o + 1024 + c] = h;
    out[o + 2048 + c] = l;
}
__global__ void k_splitAo(const float* __restrict__ src, __nv_bfloat16* __restrict__ out) {
    int i = blockIdx.x * 256 + threadIdx.x;
    if (i >= BB * NR * CC) return;
    int c = i & 1023;
    int t = i >> 10;
    float v = src[i];
    __nv_bfloat16 h = __float2bfloat16(v);
    __nv_bfloat16 l = __float2bfloat16(v - __bfloat162float(h));
    size_t o = (size_t)t * GK;
    out[o + c] = h;
    out[o + 1024 + c] = h;
    out[o + 2048 + c] = l;
}

// ------------------------- tensor GEMM via mma.sync bf16 -------------------
#define PITCH 40
#define KITERS (GK / 32)

__global__ void __launch_bounds__(256, 2) k_mgemm(
    const __nv_bfloat16* __restrict__ A, const __nv_bfloat16* __restrict__ Bm,
    const float* __restrict__ bias, float* __restrict__ C,
    int M, int N, size_t aBatch, size_t cBatch)
{
    __shared__ __nv_bfloat16 Asm[2][128 * PITCH];
    __shared__ __nv_bfloat16 Bsm[2][128 * PITCH];

    int tid = threadIdx.x, wid = tid >> 5, lane = tid & 31;
    int bm = blockIdx.y * 128, bn = blockIdx.x * 128, b = blockIdx.z;
    int wm = wid >> 2, wn = wid & 3;
    const __nv_bfloat16* Ab = A + (size_t)b * aBatch;

    int lr = tid >> 1, lc = (tid & 1) * 16;
    bool aok = (bm + lr < M);
    const uint4* aG = (const uint4*)(Ab + (size_t)(aok ? bm + lr : 0) * GK + lc);
    const uint4* bG = (const uint4*)(Bm + (size_t)(bn + lr) * GK + lc);
    const uint32_t BUF = 128 * PITCH * 2;

    uint32_t aL = s2u(&Asm[0][0]) +
                  ((wm * 64 + (lane & 15)) * PITCH + (lane >> 4) * 8) * 2;
    uint32_t bL = s2u(&Bsm[0][0]) +
                  ((wn * 32 + (lane & 7)) * PITCH + ((lane >> 3) & 1) * 8) * 2;

    float acc[4][4][4];
#pragma unroll
    for (int i = 0; i < 4; i++)
#pragma unroll
        for (int j = 0; j < 4; j++)
#pragma unroll
            for (int r = 0; r < 4; r++) acc[i][j][r] = 0.f;

    {
        uint4 a0 = aok ? aG[0] : make_uint4(0, 0, 0, 0);
        uint4 a1 = aok ? aG[1] : make_uint4(0, 0, 0, 0);
        uint4 b0 = bG[0], b1 = bG[1];
        *(uint4*)(Asm[0] + lr * PITCH + lc) = a0;
        *(uint4*)(Asm[0] + lr * PITCH + lc + 8) = a1;
        *(uint4*)(Bsm[0] + lr * PITCH + lc) = b0;
        *(uint4*)(Bsm[0] + lr * PITCH + lc + 8) = b1;
    }
    __syncthreads();

    for (int kt = 0; kt < KITERS; kt++) {
        int s = kt & 1;
        uint4 na0, na1, nb0, nb1;
        bool more = (kt + 1 < KITERS);
        if (more) {
            const uint4* ag = (const uint4*)((const __nv_bfloat16*)aG + (kt + 1) * 32);
            const uint4* bg = (const uint4*)((const __nv_bfloat16*)bG + (kt + 1) * 32);
            na0 = aok ? ag[0] : make_uint4(0, 0, 0, 0);
            na1 = aok ? ag[1] : make_uint4(0, 0, 0, 0);
            nb0 = bg[0]; nb1 = bg[1];
        }

        uint32_t aBase = aL + s * BUF, bBase = bL + s * BUF;
#pragma unroll
        for (int k16 = 0; k16 < 2; k16++) {
            uint32_t af[4][4], bf[4][2];
#pragma unroll
            for (int i = 0; i < 4; i++)
                LDSM4(af[i][0], af[i][1], af[i][2], af[i][3],
                      aBase + (i * 16 * PITCH + k16 * 16) * 2);
#pragma unroll
            for (int j = 0; j < 4; j++)
                LDSM2(bf[j][0], bf[j][1],
                      bBase + (j * 8 * PITCH + k16 * 16) * 2);
#pragma unroll
            for (int i = 0; i < 4; i++)
#pragma unroll
                for (int j = 0; j < 4; j++)
                    MMA16816(acc[i][j][0], acc[i][j][1], acc[i][j][2], acc[i][j][3],
                             af[i][0], af[i][1], af[i][2], af[i][3],
                             bf[j][0], bf[j][1]);
        }

        if (more) {
            int d = s ^ 1;
            *(uint4*)((char*)(Asm[0] + lr * PITCH + lc) + d * BUF) = na0;
            *(uint4*)((char*)(Asm[0] + lr * PITCH + lc + 8) + d * BUF) = na1;
            *(uint4*)((char*)(Bsm[0] + lr * PITCH + lc) + d * BUF) = nb0;
            *(uint4*)((char*)(Bsm[0] + lr * PITCH + lc + 8) + d * BUF) = nb1;
        }
        __syncthreads();
    }

    float* Cb = C + (size_t)b * cBatch;
    int rq = lane >> 2, cq = (lane & 3) * 2;
#pragma unroll
    for (int i = 0; i < 4; i++) {
#pragma unroll
        for (int j = 0; j < 4; j++) {
            int col = bn + wn * 32 + j * 8 + cq;
            float b0 = bias[col], b1 = bias[col + 1];
            int r0 = bm + wm * 64 + i * 16 + rq;
            if (r0 < M) {
                float2 v = make_float2(acc[i][j][0] + b0, acc[i][j][1] + b1);
                *(float2*)(Cb + (size_t)r0 * N + col) = v;
            }
            if (r0 + 8 < M) {
                float2 v = make_float2(acc[i][j][2] + b0, acc[i][j][3] + b1);
                *(float2*)(Cb + (size_t)(r0 + 8) * N + col) = v;
            }
        }
    }
}

// ------------------------- stage 5: l2norm + scale + rope (-> bf16) --------
__global__ void k_qkprep(const float* __restrict__ rope, const float* __restrict__ slog) {
    int i = blockIdx.x, b = blockIdx.y;
    int h = threadIdx.x >> 5, p = threadIdx.x & 31;
    int li = g_idx[b * NR + i];
    const float* base = g_qkv + ((size_t)b * NR + i) * QKVW;
    float2 q = *(const float2*)(base + h * 64 + 2 * p);
    float2 kk = *(const float2*)(base + CC + h * 64 + 2 * p);
    float2 vv = *(const float2*)(base + 2 * CC + h * 64 + 2 * p);
    float nq = warpSumF(q.x * q.x + q.y * q.y);
    float nk = warpSumF(kk.x * kk.x + kk.y * kk.y);
    float sm = __expf(fminf(slog[h], 4.6051701859880914f));
    float qs = sm / fmaxf(sqrtf(nq), 1e-12f);
    float ks = 1.f / fmaxf(sqrtf(nk), 1e-12f);
    float cv = rope[(size_t)li * 32 + p];
    float sv = rope[(size_t)LL * 32 + (size_t)li * 32 + p];
    float q0 = q.x * qs, q1 = q.y * qs;
    float k0 = kk.x * ks, k1 = kk.y * ks;
    size_t off = (((size_t)b * NHH + h) * NR + i) * DHH + 2 * p;
    *(__nv_bfloat162*)(g_qb + off) =
        __floats2bfloat162_rn(cv * q0 - sv * q1, sv * q0 + cv * q1);
    *(__nv_bfloat162*)(g_kb + off) =
        __floats2bfloat162_rn(cv * k0 - sv * k1, sv * k0 + cv * k1);
    *(__nv_bfloat162*)(g_vb + ((size_t)b * NR + i) * CC + h * 64 + 2 * p) =
        __floats2bfloat162_rn(vv.x, vv.y);
}

// ------------------------- stage 6: tensor-core flash attention ------------
#define FAP 72                    // smem pitch (bf16) for 64-wide rows
#define NCHUNK 26                 // ceil(NR/64)

__global__ void __launch_bounds__(128, 3) k_fattn() {
    __shared__ __nv_bfloat16 Qs[64 * FAP];
    __shared__ __nv_bfloat16 Ks[2][64 * FAP];
    __shared__ __nv_bfloat16 Vs[2][64 * FAP];
    int tid = threadIdx.x, wid = tid >> 5, lane = tid & 31;
    int qbase = blockIdx.x * 64;
    int h = blockIdx.y, b = blockIdx.z;
    const __nv_bfloat16* Qg = g_qb + ((size_t)(b * NHH + h)) * NR * DHH;
    const __nv_bfloat16* Kg = g_kb + ((size_t)(b * NHH + h)) * NR * DHH;
    const __nv_bfloat16* Vg = g_vb + (size_t)b * NR * CC + h * 64;

    const uint4 z4 = make_uint4(0, 0, 0, 0);
    int lrow = tid >> 1, lhalf = tid & 1;     // loader: row 0..63, 32-elem half

    {   // Q tile: each loader thread covers 32 bf16 = 4 x uint4
        int qi = qbase + lrow;
        const uint4* src = (const uint4*)(Qg + (size_t)(qi < NR ? qi : 0) * DHH + lhalf * 32);
        uint4* dst = (uint4*)&Qs[lrow * FAP + lhalf * 32];
#pragma unroll
        for (int t = 0; t < 4; t++) dst[t] = (qi < NR) ? src[t] : z4;
    }
    {   // K/V chunk 0 (rows < NR always)
        const uint4* ks = (const uint4*)(Kg + (size_t)lrow * DHH + lhalf * 32);
        const uint4* vs = (const uint4*)(Vg + (size_t)lrow * CC + lhalf * 32);
        uint4* kd = (uint4*)&Ks[0][lrow * FAP + lhalf * 32];
        uint4* vd = (uint4*)&Vs[0][lrow * FAP + lhalf * 32];
#pragma unroll
        for (int t = 0; t < 4; t++) { kd[t] = ks[t]; vd[t] = vs[t]; }
    }
    __syncthreads();

    // persistent Q fragments (warp owns q rows qbase + wid*16 .. +15)
    uint32_t qf[4][4];
    uint32_t qaddr = s2u(Qs) + ((wid * 16 + (lane & 15)) * FAP) * 2;
#pragma unroll
    for (int c = 0; c < 4; c++)
        LDSM4(qf[c][0], qf[c][1], qf[c][2], qf[c][3],
              qaddr + (16 * c + (lane >> 4) * 8) * 2);

    float m0 = -1e30f, m1 = -1e30f, l0 = 0.f, l1 = 0.f;
    float o[8][4];
#pragma unroll
    for (int j = 0; j < 8; j++)
#pragma unroll
        for (int r = 0; r < 4; r++) o[j][r] = 0.f;

    for (int kt = 0; kt < NCHUNK; kt++) {
        int s = kt & 1;
        // prefetch next chunk into registers
        uint4 nk[4], nv[4];
        bool more = (kt + 1 < NCHUNK);
        if (more) {
            int kc = (kt + 1) * 64 + lrow;
            bool ok = kc < NR;
            const uint4* ks = (const uint4*)(Kg + (size_t)(ok ? kc : 0) * DHH + lhalf * 32);
            const uint4* vs = (const uint4*)(Vg + (size_t)(ok ? kc : 0) * CC + lhalf * 32);
#pragma unroll
            for (int t = 0; t < 4; t++) {
                nk[t] = ok ? ks[t] : z4;
                nv[t] = ok ? vs[t] : z4;
            }
        }

        uint32_t kb = s2u(&Ks[s][0]);
        uint32_t vb = s2u(&Vs[s][0]);

        // S = Q K^T  (8 kv n-tiles x 4 dh k-chunks)
        float sc[8][4];
#pragma unroll
        for (int j = 0; j < 8; j++) {
            sc[j][0] = sc[j][1] = sc[j][2] = sc[j][3] = 0.f;
#pragma unroll
            for (int c = 0; c < 4; c++) {
                uint32_t b0, b1;
                LDSM2(b0, b1, kb + ((8 * j + (lane & 7)) * FAP +
                                    16 * c + ((lane >> 3) & 1) * 8) * 2);
                MMA16816(sc[j][0], sc[j][1], sc[j][2], sc[j][3],
                         qf[c][0], qf[c][1], qf[c][2], qf[c][3], b0, b1);
            }
        }

        // mask (last chunk only)
        if (kt * 64 + 64 > NR) {
#pragma unroll
            for (int j = 0; j < 8; j++) {
                int col = kt * 64 + 8 * j + 2 * (lane & 3);
                if (col >= NR)     { sc[j][0] = -1e30f; sc[j][2] = -1e30f; }
                if (col + 1 >= NR) { sc[j][1] = -1e30f; sc[j][3] = -1e30f; }
            }
        }

        // online softmax (rows r = lane>>2 and r+8)
        float rm0 = -1e30f, rm1 = -1e30f;
#pragma unroll
        for (int j = 0; j < 8; j++) {
            rm0 = fmaxf(rm0, fmaxf(sc[j][0], sc[j][1]));
            rm1 = fmaxf(rm1, fmaxf(sc[j][2], sc[j][3]));
        }
        rm0 = fmaxf(rm0, __shfl_xor_sync(0xffffffffu, rm0, 1));
        rm0 = fmaxf(rm0, __shfl_xor_sync(0xffffffffu, rm0, 2));
        rm1 = fmaxf(rm1, __shfl_xor_sync(0xffffffffu, rm1, 1));
        rm1 = fmaxf(rm1, __shfl_xor_sync(0xffffffffu, rm1, 2));
        float mn0 = fmaxf(m0, rm0), mn1 = fmaxf(m1, rm1);
        float cr0 = __expf(m0 - mn0), cr1 = __expf(m1 - mn1);
        m0 = mn0; m1 = mn1;
        float s0 = 0.f, s1 = 0.f;
#pragma unroll
        for (int j = 0; j < 8; j++) {
            sc[j][0] = __expf(sc[j][0] - mn0);
            sc[j][1] = __expf(sc[j][1] - mn0);
            sc[j][2] = __expf(sc[j][2] - mn1);
            sc[j][3] = __expf(sc[j][3] - mn1);
            s0 += sc[j][0] + sc[j][1];
            s1 += sc[j][2] + sc[j][3];
        }
        s0 += __shfl_xor_sync(0xffffffffu, s0, 1);
        s0 += __shfl_xor_sync(0xffffffffu, s0, 2);
        s1 += __shfl_xor_sync(0xffffffffu, s1, 1);
        s1 += __shfl_xor_sync(0xffffffffu, s1, 2);
        l0 = l0 * cr0 + s0;
        l1 = l1 * cr1 + s1;
#pragma unroll
        for (int j = 0; j < 8; j++) {
            o[j][0] *= cr0; o[j][1] *= cr0;
            o[j][2] *= cr1; o[j][3] *= cr1;
        }

        // repack P accumulators -> A fragments (kv contraction)
        uint32_t pa[4][4];
#pragma unroll
        for (int c = 0; c < 4; c++) {
            pa[c][0] = packbf(sc[2 * c][0], sc[2 * c][1]);
            pa[c][1] = packbf(sc[2 * c][2], sc[2 * c][3]);
            pa[c][2] = packbf(sc[2 * c + 1][0], sc[2 * c + 1][1]);
            pa[c][3] = packbf(sc[2 * c + 1][2], sc[2 * c + 1][3]);
        }

        // O += P V  (8 dh n-tiles x 4 kv k-chunks)
#pragma unroll
        for (int j = 0; j < 8; j++) {
#pragma unroll
            for (int c = 0; c < 4; c++) {
                uint32_t b0, b1;
                LDSM2T(b0, b1, vb + ((16 * c + (lane & 15)) * FAP + 8 * j) * 2);
                MMA16816(o[j][0], o[j][1], o[j][2], o[j][3],
                         pa[c][0], pa[c][1], pa[c][2], pa[c][3], b0, b1);
            }
        }

        if (more) {
            int d = s ^ 1;
            uint4* kd = (uint4*)&Ks[d][lrow * FAP + lhalf * 32];
            uint4* vd = (uint4*)&Vs[d][lrow * FAP + lhalf * 32];
#pragma unroll
            for (int t = 0; t < 4; t++) { kd[t] = nk[t]; vd[t] = nv[t]; }
        }
        __syncthreads();
    }

    // epilogue
    int r0 = qbase + wid * 16 + (lane >> 2);
    float inv0 = 1.f / l0, inv1 = 1.f / l1;
#pragma unroll
    for (int j = 0; j < 8; j++) {
        int col = h * 64 + 8 * j + 2 * (lane & 3);
        if (r0 < NR)
            *(float2*)&g_o[((size_t)b * NR + r0) * CC + col] =
                make_float2(o[j][0] * inv0, o[j][1] * inv0);
        if (r0 + 8 < NR)
            *(float2*)&g_o[((size_t)b * NR + r0 + 8) * CC + col] =
                make_float2(o[j][2] * inv1, o[j][3] * inv1);
    }
}

// ------------------------- stage 7: residual + upsample + scatter ----------
__global__ void k_out1(const float* __restrict__ x, const float* __restrict__ cached,
                       float* __restrict__ out) {
    size_t e = ((size_t)blockIdx.x * 256 + threadIdx.x) * 4;
    int b = (int)(e >> 22);
    int rem = (int)(e & ((1u << 22) - 1));
    int l = rem >> 10, c = rem & 1023;
    int hh = l >> 6, ww = l & 63;
    size_t uoff = ((((size_t)b * 32 + (hh >> 1)) * 32) + (ww >> 1)) * 1024 + c;
    float4 xv = *(const float4*)(x + e);
    float4 uv = *(const float4*)(cached + uoff);
    *(float4*)(out + e) = make_float4(xv.x + uv.x, xv.y + uv.y, xv.z + uv.z, xv.w + uv.w);
}

__global__ void k_out2(const float* __restrict__ x, float* __restrict__ out) {
    int i = blockIdx.x, b = blockIdx.y;
    int li = g_idx[b * NR + i];
    int c = threadIdx.x * 4;
    size_t xoff = ((size_t)b * LL + li) * CC + c;
    float4 xv = *(const float4*)(x + xoff);
    float4 pv = *(const float4*)(g_pr + ((size_t)b * NR + i) * CC + c);
    *(float4*)(out + xoff) = make_float4(xv.x + pv.x, xv.y + pv.y, xv.z + pv.z, xv.w + pv.w);
}

// ------------------------- launcher ----------------------------------------
extern "C" void kernel_launch(void* const* d_in, const int* in_sizes, int n_in,
                              void* d_out, int out_size) {
    const float* x      = (const float*)d_in[0];
    const float* cached = (const float*)d_in[1];
    const float* Wqkv   = (const float*)d_in[2];
    const float* qb     = (const float*)d_in[3];
    const float* vb     = (const float*)d_in[4];
    const float* Wproj  = (const float*)d_in[5];
    const float* bp     = (const float*)d_in[6];
    const float* slog   = (const float*)d_in[7];
    const float* rope   = (const float*)d_in[8];
    float* out = (float*)d_out;

    void *p_qkv, *p_o, *p_pr, *p_bias, *p_ax, *p_wq, *p_wp, *p_ao;
    cudaGetSymbolAddress(&p_qkv, g_qkv);
    cudaGetSymbolAddress(&p_o, g_o);
    cudaGetSymbolAddress(&p_pr, g_pr);
    cudaGetSymbolAddress(&p_bias, g_bias);
    cudaGetSymbolAddress(&p_ax, g_ax);
    cudaGetSymbolAddress(&p_wq, g_wq);
    cudaGetSymbolAddress(&p_wp, g_wp);
    cudaGetSymbolAddress(&p_ao, g_ao);

    k_colsum<<<dim3(4, 8, BB), 256>>>(x);
    k_meanfin<<<8, 256>>>();
    k_mse<<<dim3(LL, BB), 256>>>(x);
    k_topk<<<BB, 1024>>>();
    k_bias<<<12, 256>>>(qb, vb);

    // pack split-bf16 operands
    k_splitB<<<(QKVW * CC + 255) / 256, 256>>>(Wqkv, (__nv_bfloat16*)p_wq, QKVW * CC);
    k_splitB<<<(CC * CC + 255) / 256, 256>>>(Wproj, (__nv_bfloat16*)p_wp, CC * CC);
    k_splitAx<<<(BB * NR * CC + 255) / 256, 256>>>(x, (__nv_bfloat16*)p_ax);

    // QKV projection (tensor)
    k_mgemm<<<dim3(QKVW / 128, 13, BB), 256>>>(
        (const __nv_bfloat16*)p_ax, (const __nv_bfloat16*)p_wq,
        (const float*)p_bias, (float*)p_qkv,
        NR, QKVW, (size_t)NR * GK, (size_t)NR * QKVW);

    k_qkprep<<<dim3(NR, BB), 512>>>(rope, slog);

    // tensor-core flash attention
    k_fattn<<<dim3((NR + 63) / 64, NHH, BB), 128>>>();

    // output projection (tensor)
    k_splitAo<<<(BB * NR * CC + 255) / 256, 256>>>((const float*)p_o, (__nv_bfloat16*)p_ao);
    k_mgemm<<<dim3(CC / 128, 13, BB), 256>>>(
        (const __nv_bfloat16*)p_ao, (const __nv_bfloat16*)p_wp,
        bp, (float*)p_pr,
        NR, CC, (size_t)NR * GK, (size_t)NR * CC);

    k_out1<<<8192, 256>>>(x, cached, out);
    k_out2<<<dim3(NR, BB), 256>>>(x, out);
}

// round 9
// speedup vs baseline: 2.7856x; 2.0979x over previous
#include <cuda_runtime.h>
#include <cuda_fp16.h>
#include <math.h>
#include <stdint.h>

#define BB 2
#define LL 4096
#define CC 1024
#define NHH 16
#define DHH 64
#define NR 1638
#define QKVW 3072
#define GK 2048          // packed split-K (2 x 1024), fp16 [hi|lo] x [hi|hi]

// ------------------------- scratch (device globals; no runtime alloc) -------
__device__ float g_mean[BB * CC];
__device__ double g_part[BB * 8 * CC];
__device__ float g_mse[BB * LL];
__device__ int g_idx[BB * NR];
__device__ float g_bias[QKVW];
__device__ float g_qkv[(size_t)BB * NR * QKVW];   // (b, i, 3*C) fp32
__device__ float g_pr[(size_t)BB * NR * CC];
// fp16 attention operands
__device__ __half g_qh[(size_t)BB * NHH * NR * DHH];
__device__ __half g_kh[(size_t)BB * NHH * NR * DHH];
__device__ __half g_vh[(size_t)BB * NR * CC];
// fp16 split-packed GEMM operands
__device__ __half g_ax[(size_t)BB * NR * GK];   // x[idx]   [hi|lo]
__device__ __half g_wq[(size_t)QKVW * GK];      // Wqkv     [hi|hi]
__device__ __half g_wp[(size_t)CC * GK];        // Wproj    [hi|hi]
__device__ __half g_ao[(size_t)BB * NR * GK];   // attn out [hi|lo] (written by fattn)

// ------------------------- helpers -----------------------------------------
__device__ __forceinline__ float warpSumF(float v) {
#pragma unroll
    for (int m = 16; m; m >>= 1) v += __shfl_xor_sync(0xffffffffu, v, m);
    return v;
}
__device__ __forceinline__ double warpSumD(double v) {
#pragma unroll
    for (int m = 16; m; m >>= 1) v += __shfl_xor_sync(0xffffffffu, v, m);
    return v;
}
__device__ __forceinline__ uint32_t s2u(const void* p) {
    uint32_t a;
    asm("{ .reg .u64 t; cvta.to.shared.u64 t, %1; cvt.u32.u64 %0, t; }" : "=r"(a) : "l"(p));
    return a;
}
__device__ __forceinline__ uint32_t packh(float a, float b) {
    __half2 t = __floats2half2_rn(a, b);   // x=a (low), y=b (high)
    return *(uint32_t*)&t;
}
#define LDSM4(d0, d1, d2, d3, addr) \
    asm volatile("ldmatrix.sync.aligned.m8n8.x4.shared.b16 {%0,%1,%2,%3}, [%4];" \
                 : "=r"(d0), "=r"(d1), "=r"(d2), "=r"(d3) : "r"(addr))
#define LDSM2(d0, d1, addr) \
    asm volatile("ldmatrix.sync.aligned.m8n8.x2.shared.b16 {%0,%1}, [%2];" \
                 : "=r"(d0), "=r"(d1) : "r"(addr))
#define LDSM2T(d0, d1, addr) \
    asm volatile("ldmatrix.sync.aligned.m8n8.x2.trans.shared.b16 {%0,%1}, [%2];" \
                 : "=r"(d0), "=r"(d1) : "r"(addr))
#define MMA16816(c0, c1, c2, c3, a0, a1, a2, a3, b0, b1) \
    asm volatile("mma.sync.aligned.m16n8k16.row.col.f32.f16.f16.f32 " \
                 "{%0,%1,%2,%3}, {%4,%5,%6,%7}, {%8,%9}, {%0,%1,%2,%3};" \
                 : "+f"(c0), "+f"(c1), "+f"(c2), "+f"(c3) \
                 : "r"(a0), "r"(a1), "r"(a2), "r"(a3), "r"(b0), "r"(b1))

// ------------------------- stage 1: mean over L (fp64 accum) ---------------
__global__ void k_colsum(const float* __restrict__ x) {
    int c = blockIdx.x * 256 + threadIdx.x;
    int b = blockIdx.z;
    int l0 = blockIdx.y * 512;
    const float* p = x + ((size_t)b * LL + l0) * CC + c;
    double a0 = 0, a1 = 0, a2 = 0, a3 = 0;
#pragma unroll 4
    for (int l = 0; l < 512; l += 4) {
        a0 += (double)p[(size_t)(l + 0) * CC];
        a1 += (double)p[(size_t)(l + 1) * CC];
        a2 += (double)p[(size_t)(l + 2) * CC];
        a3 += (double)p[(size_t)(l + 3) * CC];
    }
    g_part[(b * 8 + blockIdx.y) * CC + c] = a0 + a1 + a2 + a3;
}

__global__ void k_meanfin() {
    int i = blockIdx.x * 256 + threadIdx.x;
    int b = i >> 10, c = i & 1023;
    double s = 0;
#pragma unroll
    for (int k = 0; k < 8; k++) s += g_part[(b * 8 + k) * CC + c];
    g_mean[b * CC + c] = (float)(s * (1.0 / (double)LL));
}

// ------------------------- stage 2: per-row mse (fp64 accum) ---------------
__global__ void k_mse(const float* __restrict__ x) {
    int l = blockIdx.x, b = blockIdx.y;
    const float* xr = x + ((size_t)b * LL + l) * CC;
    double acc = 0;
#pragma unroll
    for (int k = 0; k < 4; k++) {
        int c = threadIdx.x + k * 256;
        double d = (double)xr[c] - (double)g_mean[b * CC + c];
        acc += d * d;
    }
    acc = warpSumD(acc);
    __shared__ double red[8];
    if ((threadIdx.x & 31) == 0) red[threadIdx.x >> 5] = acc;
    __syncthreads();
    if (threadIdx.x == 0) {
        double t = 0;
#pragma unroll
        for (int w = 0; w < 8; w++) t += red[w];
        g_mse[b * LL + l] = (float)t;
    }
}

// ------------------------- stage 3: top-NR radix select (parallel scan) ----
__global__ void k_topk() {
    __shared__ unsigned int hist[256];
    __shared__ unsigned int suf[256];
    __shared__ unsigned int sh_pref, sh_rank, sh_cgt, sh_ceq;
    int b = blockIdx.x, tid = threadIdx.x;   // 1024 threads
    unsigned int key[4];
#pragma unroll
    for (int k = 0; k < 4; k++)
        key[k] = __float_as_uint(g_mse[b * LL + tid * 4 + k]);  // mse>=0: monotonic bits
    if (tid == 0) { sh_pref = 0; sh_rank = NR; }
#pragma unroll
    for (int pass = 0; pass < 4; pass++) {
        int shift = 24 - pass * 8;
        if (tid < 256) hist[tid] = 0;
        __syncthreads();
        unsigned int pref = sh_pref, r = sh_rank;
        unsigned int himask = (pass == 0) ? 0u : (0xFFFFFFFFu << (shift + 8));
#pragma unroll
        for (int k = 0; k < 4; k++)
            if ((key[k] & himask) == pref)
                atomicAdd(&hist[(key[k] >> shift) & 255], 1u);
        __syncthreads();
        if (tid < 256) suf[tid] = hist[tid];
        __syncthreads();
        // suffix sum: suf[t] = sum_{j>=t} hist[j]
#pragma unroll
        for (int off = 1; off < 256; off <<= 1) {
            unsigned int t = 0;
            if (tid < 256 && tid + off < 256) t = suf[tid + off];
            __syncthreads();
            if (tid < 256) suf[tid] += t;
            __syncthreads();
        }
        if (tid < 256) {
            unsigned int hi = (tid == 255) ? 0u : suf[tid + 1];
            if (suf[tid] >= r && hi < r) {
                sh_pref = pref | ((unsigned int)tid << shift);
                sh_rank = r - hi;
            }
        }
        __syncthreads();
    }
    if (tid == 0) { sh_cgt = 0; sh_ceq = 0; }
    __syncthreads();
    unsigned int thr = sh_pref, need = sh_rank;
    int ngt = NR - (int)need;
#pragma unroll
    for (int k = 0; k < 4; k++) {
        if (key[k] > thr) {
            unsigned int p = atomicAdd(&sh_cgt, 1u);
            g_idx[b * NR + p] = tid * 4 + k;
        } else if (key[k] == thr) {
            unsigned int p = atomicAdd(&sh_ceq, 1u);
            if (p < need) g_idx[b * NR + ngt + p] = tid * 4 + k;
        }
    }
}

// ------------------------- stage 4: fused bias ------------------------------
__global__ void k_bias(const float* __restrict__ qb, const float* __restrict__ vb) {
    int i = blockIdx.x * 256 + threadIdx.x;
    if (i < QKVW) g_bias[i] = (i < CC) ? qb[i] : ((i < 2 * CC) ? 0.f : vb[i - 2 * CC]);
}

// ------------------------- split/pack kernels (fp16 2-term) -----------------
__global__ void k_splitB(const float* __restrict__ W, __half* __restrict__ out, int total) {
    int i = blockIdx.x * 256 + threadIdx.x;
    if (i >= total) return;
    int r = i >> 10, c = i & 1023;
    __half h = __float2half(W[i]);
    size_t o = (size_t)r * GK;
    out[o + c] = h;
    out[o + 1024 + c] = h;
}
__global__ void k_splitAx(const float* __restrict__ x, __half* __restrict__ out) {
    int i = blockIdx.x * 256 + threadIdx.x;
    if (i >= BB * NR * CC) return;
    int c = i & 1023;
    int t = i >> 10;
    int r = t % NR, b = t / NR;
    int li = g_idx[b * NR + r];
    float v = x[((size_t)b * LL + li) * CC + c];
    __half h = __float2half(v);
    __half l = __float2half(v - __half2float(h));
    size_t o = (size_t)t * GK;
    out[o + c] = h;
    out[o + 1024 + c] = l;
}

// ------------------------- tensor GEMM via mma.sync fp16 -------------------
// C(M,N) = A(M,GK) @ B(N,GK)^T + bias.  BM=128 BN=128 BK=32, 8 warps.
#define PITCH 40
#define KITERS (GK / 32)   // 64

__global__ void __launch_bounds__(256, 2) k_mgemm(
    const __half* __restrict__ A, const __half* __restrict__ Bm,
    const float* __restrict__ bias, float* __restrict__ C,
    int M, int N, size_t aBatch, size_t cBatch)
{
    __shared__ __half Asm[2][128 * PITCH];
    __shared__ __half Bsm[2][128 * PITCH];

    int tid = threadIdx.x, wid = tid >> 5, lane = tid & 31;
    int bm = blockIdx.y * 128, bn = blockIdx.x * 128, b = blockIdx.z;
    int wm = wid >> 2, wn = wid & 3;
    const __half* Ab = A + (size_t)b * aBatch;

    int lr = tid >> 1, lc = (tid & 1) * 16;
    bool aok = (bm + lr < M);
    const uint4* aG = (const uint4*)(Ab + (size_t)(aok ? bm + lr : 0) * GK + lc);
    const uint4* bG = (const uint4*)(Bm + (size_t)(bn + lr) * GK + lc);
    const uint32_t BUF = 128 * PITCH * 2;

    uint32_t aL = s2u(&Asm[0][0]) +
                  ((wm * 64 + (lane & 15)) * PITCH + (lane >> 4) * 8) * 2;
    uint32_t bL = s2u(&Bsm[0][0]) +
                  ((wn * 32 + (lane & 7)) * PITCH + ((lane >> 3) & 1) * 8) * 2;

    float acc[4][4][4];
#pragma unroll
    for (int i = 0; i < 4; i++)
#pragma unroll
        for (int j = 0; j < 4; j++)
#pragma unroll
            for (int r = 0; r < 4; r++) acc[i][j][r] = 0.f;

    {
        uint4 a0 = aok ? aG[0] : make_uint4(0, 0, 0, 0);
        uint4 a1 = aok ? aG[1] : make_uint4(0, 0, 0, 0);
        uint4 b0 = bG[0], b1 = bG[1];
        *(uint4*)(Asm[0] + lr * PITCH + lc) = a0;
        *(uint4*)(Asm[0] + lr * PITCH + lc + 8) = a1;
        *(uint4*)(Bsm[0] + lr * PITCH + lc) = b0;
        *(uint4*)(Bsm[0] + lr * PITCH + lc + 8) = b1;
    }
    __syncthreads();

    for (int kt = 0; kt < KITERS; kt++) {
        int s = kt & 1;
        uint4 na0, na1, nb0, nb1;
        bool more = (kt + 1 < KITERS);
        if (more) {
            const uint4* ag = (const uint4*)((const __half*)aG + (kt + 1) * 32);
            const uint4* bg = (const uint4*)((const __half*)bG + (kt + 1) * 32);
            na0 = aok ? ag[0] : make_uint4(0, 0, 0, 0);
            na1 = aok ? ag[1] : make_uint4(0, 0, 0, 0);
            nb0 = bg[0]; nb1 = bg[1];
        }

        uint32_t aBase = aL + s * BUF, bBase = bL + s * BUF;
#pragma unroll
        for (int k16 = 0; k16 < 2; k16++) {
            uint32_t af[4][4], bf[4][2];
#pragma unroll
            for (int i = 0; i < 4; i++)
                LDSM4(af[i][0], af[i][1], af[i][2], af[i][3],
                      aBase + (i * 16 * PITCH + k16 * 16) * 2);
#pragma unroll
            for (int j = 0; j < 4; j++)
                LDSM2(bf[j][0], bf[j][1],
                      bBase + (j * 8 * PITCH + k16 * 16) * 2);
#pragma unroll
            for (int i = 0; i < 4; i++)
#pragma unroll
                for (int j = 0; j < 4; j++)
                    MMA16816(acc[i][j][0], acc[i][j][1], acc[i][j][2], acc[i][j][3],
                             af[i][0], af[i][1], af[i][2], af[i][3],
                             bf[j][0], bf[j][1]);
        }

        if (more) {
            int d = s ^ 1;
            *(uint4*)((char*)(Asm[0] + lr * PITCH + lc) + d * BUF) = na0;
            *(uint4*)((char*)(Asm[0] + lr * PITCH + lc + 8) + d * BUF) = na1;
            *(uint4*)((char*)(Bsm[0] + lr * PITCH + lc) + d * BUF) = nb0;
            *(uint4*)((char*)(Bsm[0] + lr * PITCH + lc + 8) + d * BUF) = nb1;
        }
        __syncthreads();
    }

    float* Cb = C + (size_t)b * cBatch;
    int rq = lane >> 2, cq = (lane & 3) * 2;
#pragma unroll
    for (int i = 0; i < 4; i++) {
#pragma unroll
        for (int j = 0; j < 4; j++) {
            int col = bn + wn * 32 + j * 8 + cq;
            float b0 = bias[col], b1 = bias[col + 1];
            int r0 = bm + wm * 64 + i * 16 + rq;
            if (r0 < M) {
                float2 v = make_float2(acc[i][j][0] + b0, acc[i][j][1] + b1);
                *(float2*)(Cb + (size_t)r0 * N + col) = v;
            }
            if (r0 + 8 < M) {
                float2 v = make_float2(acc[i][j][2] + b0, acc[i][j][3] + b1);
                *(float2*)(Cb + (size_t)(r0 + 8) * N + col) = v;
            }
        }
    }
}

// ------------------------- stage 5: l2norm + scale + rope (-> fp16) --------
__global__ void k_qkprep(const float* __restrict__ rope, const float* __restrict__ slog) {
    int i = blockIdx.x, b = blockIdx.y;
    int h = threadIdx.x >> 5, p = threadIdx.x & 31;
    int li = g_idx[b * NR + i];
    const float* base = g_qkv + ((size_t)b * NR + i) * QKVW;
    float2 q = *(const float2*)(base + h * 64 + 2 * p);
    float2 kk = *(const float2*)(base + CC + h * 64 + 2 * p);
    float2 vv = *(const float2*)(base + 2 * CC + h * 64 + 2 * p);
    float nq = warpSumF(q.x * q.x + q.y * q.y);
    float nk = warpSumF(kk.x * kk.x + kk.y * kk.y);
    float sm = __expf(fminf(slog[h], 4.6051701859880914f));
    float qs = sm / fmaxf(sqrtf(nq), 1e-12f);
    float ks = 1.f / fmaxf(sqrtf(nk), 1e-12f);
    float cv = rope[(size_t)li * 32 + p];
    float sv = rope[(size_t)LL * 32 + (size_t)li * 32 + p];
    float q0 = q.x * qs, q1 = q.y * qs;
    float k0 = kk.x * ks, k1 = kk.y * ks;
    size_t off = (((size_t)b * NHH + h) * NR + i) * DHH + 2 * p;
    *(__half2*)(g_qh + off) = __floats2half2_rn(cv * q0 - sv * q1, sv * q0 + cv * q1);
    *(__half2*)(g_kh + off) = __floats2half2_rn(cv * k0 - sv * k1, sv * k0 + cv * k1);
    *(__half2*)(g_vh + ((size_t)b * NR + i) * CC + h * 64 + 2 * p) =
        __floats2half2_rn(vv.x, vv.y);
}

// ------------------------- stage 6: tensor-core flash attention ------------
// 256 threads, 8 warps, 128 q rows per CTA, 64-kv chunks, fp16 operands.
// Epilogue writes the proj-GEMM A operand [hi|lo] directly (fuses splitAo).
#define FAP 72
#define NCHUNK 26
#define FA_SMEM ((128 * FAP + 4 * 64 * FAP) * 2)

__global__ void __launch_bounds__(256, 2) k_fattn() {
    extern __shared__ __half fsm[];
    __half* Qs = fsm;                       // 128 x FAP
    __half* Ks = Qs + 128 * FAP;            // 2 x 64 x FAP
    __half* Vs = Ks + 2 * 64 * FAP;         // 2 x 64 x FAP
    int tid = threadIdx.x, wid = tid >> 5, lane = tid & 31;
    int qbase = blockIdx.x * 128;
    int h = blockIdx.y, b = blockIdx.z;
    const __half* Qg = g_qh + ((size_t)(b * NHH + h)) * NR * DHH;
    const __half* Kg = g_kh + ((size_t)(b * NHH + h)) * NR * DHH;
    const __half* Vg = g_vh + (size_t)b * NR * CC + h * 64;

    const uint4 z4 = make_uint4(0, 0, 0, 0);
    int lrow = tid >> 1, lhalf = tid & 1;     // Q loader: 128 rows x 32-elem half
    int krow = tid >> 2, kq = tid & 3;        // K/V loader: 64 rows x 16-elem quarter

    {   // Q tile: 32 halves = 4 x uint4 per thread
        int qi = qbase + lrow;
        const uint4* src = (const uint4*)(Qg + (size_t)(qi < NR ? qi : 0) * DHH + lhalf * 32);
        uint4* dst = (uint4*)&Qs[lrow * FAP + lhalf * 32];
#pragma unroll
        for (int t = 0; t < 4; t++) dst[t] = (qi < NR) ? src[t] : z4;
    }
    {   // K/V chunk 0: 16 halves = 2 x uint4 per thread (rows < NR always)
        const uint4* ks = (const uint4*)(Kg + (size_t)krow * DHH + kq * 16);
        const uint4* vs = (const uint4*)(Vg + (size_t)krow * CC + kq * 16);
        uint4* kd = (uint4*)&Ks[krow * FAP + kq * 16];
        uint4* vd = (uint4*)&Vs[krow * FAP + kq * 16];
        kd[0] = ks[0]; kd[1] = ks[1];
        vd[0] = vs[0]; vd[1] = vs[1];
    }
    __syncthreads();

    // persistent Q fragments (warp owns rows qbase + wid*16 .. +15)
    uint32_t qf[4][4];
    uint32_t qaddr = s2u(Qs) + ((wid * 16 + (lane & 15)) * FAP) * 2;
#pragma unroll
    for (int c = 0; c < 4; c++)
        LDSM4(qf[c][0], qf[c][1], qf[c][2], qf[c][3],
              qaddr + (16 * c + (lane >> 4) * 8) * 2);

    float m0 = -1e30f, m1 = -1e30f, l0 = 0.f, l1 = 0.f;
    float o[8][4];
#pragma unroll
    for (int j = 0; j < 8; j++)
#pragma unroll
        for (int r = 0; r < 4; r++) o[j][r] = 0.f;

    for (int kt = 0; kt < NCHUNK; kt++) {
        int s = kt & 1;
        uint4 nk[2], nv[2];
        bool more = (kt + 1 < NCHUNK);
        if (more) {
            int kc = (kt + 1) * 64 + krow;
            bool ok = kc < NR;
            const uint4* ks = (const uint4*)(Kg + (size_t)(ok ? kc : 0) * DHH + kq * 16);
            const uint4* vs = (const uint4*)(Vg + (size_t)(ok ? kc : 0) * CC + kq * 16);
            nk[0] = ok ? ks[0] : z4; nk[1] = ok ? ks[1] : z4;
            nv[0] = ok ? vs[0] : z4; nv[1] = ok ? vs[1] : z4;
        }

        uint32_t kb = s2u(&Ks[s * 64 * FAP]);
        uint32_t vb = s2u(&Vs[s * 64 * FAP]);

        // S = Q K^T  (8 kv n-tiles x 4 dh k-chunks)
        float sc[8][4];
#pragma unroll
        for (int j = 0; j < 8; j++) {
            sc[j][0] = sc[j][1] = sc[j][2] = sc[j][3] = 0.f;
#pragma unroll
            for (int c = 0; c < 4; c++) {
                uint32_t b0, b1;
                LDSM2(b0, b1, kb + ((8 * j + (lane & 7)) * FAP +
                                    16 * c + ((lane >> 3) & 1) * 8) * 2);
                MMA16816(sc[j][0], sc[j][1], sc[j][2], sc[j][3],
                         qf[c][0], qf[c][1], qf[c][2], qf[c][3], b0, b1);
            }
        }

        // mask (last chunk only)
        if (kt * 64 + 64 > NR) {
#pragma unroll
            for (int j = 0; j < 8; j++) {
                int col = kt * 64 + 8 * j + 2 * (lane & 3);
                if (col >= NR)     { sc[j][0] = -1e30f; sc[j][2] = -1e30f; }
                if (col + 1 >= NR) { sc[j][1] = -1e30f; sc[j][3] = -1e30f; }
            }
        }

        // online softmax (rows r = lane>>2 and r+8)
        float rm0 = -1e30f, rm1 = -1e30f;
#pragma unroll
        for (int j = 0; j < 8; j++) {
            rm0 = fmaxf(rm0, fmaxf(sc[j][0], sc[j][1]));
            rm1 = fmaxf(rm1, fmaxf(sc[j][2], sc[j][3]));
        }
        rm0 = fmaxf(rm0, __shfl_xor_sync(0xffffffffu, rm0, 1));
        rm0 = fmaxf(rm0, __shfl_xor_sync(0xffffffffu, rm0, 2));
        rm1 = fmaxf(rm1, __shfl_xor_sync(0xffffffffu, rm1, 1));
        rm1 = fmaxf(rm1, __shfl_xor_sync(0xffffffffu, rm1, 2));
        float mn0 = fmaxf(m0, rm0), mn1 = fmaxf(m1, rm1);
        float cr0 = __expf(m0 - mn0), cr1 = __expf(m1 - mn1);
        m0 = mn0; m1 = mn1;
        float s0 = 0.f, s1 = 0.f;
#pragma unroll
        for (int j = 0; j < 8; j++) {
            sc[j][0] = __expf(sc[j][0] - mn0);
            sc[j][1] = __expf(sc[j][1] - mn0);
            sc[j][2] = __expf(sc[j][2] - mn1);
            sc[j][3] = __expf(sc[j][3] - mn1);
            s0 += sc[j][0] + sc[j][1];
            s1 += sc[j][2] + sc[j][3];
        }
        s0 += __shfl_xor_sync(0xffffffffu, s0, 1);
        s0 += __shfl_xor_sync(0xffffffffu, s0, 2);
        s1 += __shfl_xor_sync(0xffffffffu, s1, 1);
        s1 += __shfl_xor_sync(0xffffffffu, s1, 2);
        l0 = l0 * cr0 + s0;
        l1 = l1 * cr1 + s1;
#pragma unroll
        for (int j = 0; j < 8; j++) {
            o[j][0] *= cr0; o[j][1] *= cr0;
            o[j][2] *= cr1; o[j][3] *= cr1;
        }

        // repack P accumulators -> A fragments (kv contraction)
        uint32_t pa[4][4];
#pragma unroll
        for (int c = 0; c < 4; c++) {
            pa[c][0] = packh(sc[2 * c][0], sc[2 * c][1]);
            pa[c][1] = packh(sc[2 * c][2], sc[2 * c][3]);
            pa[c][2] = packh(sc[2 * c + 1][0], sc[2 * c + 1][1]);
            pa[c][3] = packh(sc[2 * c + 1][2], sc[2 * c + 1][3]);
        }

        // O += P V  (8 dh n-tiles x 4 kv k-chunks)
#pragma unroll
        for (int j = 0; j < 8; j++) {
#pragma unroll
            for (int c = 0; c < 4; c++) {
                uint32_t b0, b1;
                LDSM2T(b0, b1, vb + ((16 * c + (lane & 15)) * FAP + 8 * j) * 2);
                MMA16816(o[j][0], o[j][1], o[j][2], o[j][3],
                         pa[c][0], pa[c][1], pa[c][2], pa[c][3], b0, b1);
            }
        }

        if (more) {
            int d = s ^ 1;
            uint4* kd = (uint4*)&Ks[d * 64 * FAP + krow * FAP + kq * 16];
            uint4* vd = (uint4*)&Vs[d * 64 * FAP + krow * FAP + kq * 16];
            kd[0] = nk[0]; kd[1] = nk[1];
            vd[0] = nv[0]; vd[1] = nv[1];
        }
        __syncthreads();
    }

    // epilogue: write proj A operand [hi|lo] directly (fused splitAo)
    int r0 = qbase + wid * 16 + (lane >> 2);
    float inv0 = 1.f / l0, inv1 = 1.f / l1;
#pragma unroll
    for (int j = 0; j < 8; j++) {
        int col = h * 64 + 8 * j + 2 * (lane & 3);
#pragma unroll
        for (int half = 0; half < 2; half++) {
            int r = r0 + half * 8;
            if (r >= NR) continue;
            float va = o[j][2 * half + 0] * (half ? inv1 : inv0);
            float vbv = o[j][2 * half + 1] * (half ? inv1 : inv0);
            __half ha = __float2half(va), hb = __float2half(vbv);
            __half la = __float2half(va - __half2float(ha));
            __half lb = __float2half(vbv - __half2float(hb));
            size_t base = ((size_t)b * NR + r) * GK;
            *(__half2*)&g_ao[base + col] = __halves2half2(ha, hb);
            *(__half2*)&g_ao[base + 1024 + col] = __halves2half2(la, lb);
        }
    }
}

// ------------------------- stage 7: residual + upsample + scatter ----------
__global__ void k_out1(const float* __restrict__ x, const float* __restrict__ cached,
                       float* __restrict__ out) {
    size_t e = ((size_t)blockIdx.x * 256 + threadIdx.x) * 4;
    int b = (int)(e >> 22);
    int rem = (int)(e & ((1u << 22) - 1));
    int l = rem >> 10, c = rem & 1023;
    int hh = l >> 6, ww = l & 63;
    size_t uoff = ((((size_t)b * 32 + (hh >> 1)) * 32) + (ww >> 1)) * 1024 + c;
    float4 xv = *(const float4*)(x + e);
    float4 uv = *(const float4*)(cached + uoff);
    *(float4*)(out + e) = make_float4(xv.x + uv.x, xv.y + uv.y, xv.z + uv.z, xv.w + uv.w);
}

__global__ void k_out2(const float* __restrict__ x, float* __restrict__ out) {
    int i = blockIdx.x, b = blockIdx.y;
    int li = g_idx[b * NR + i];
    int c = threadIdx.x * 4;
    size_t xoff = ((size_t)b * LL + li) * CC + c;
    float4 xv = *(const float4*)(x + xoff);
    float4 pv = *(const float4*)(g_pr + ((size_t)b * NR + i) * CC + c);
    *(float4*)(out + xoff) = make_float4(xv.x + pv.x, xv.y + pv.y, xv.z + pv.z, xv.w + pv.w);
}

// ------------------------- launcher ----------------------------------------
extern "C" void kernel_launch(void* const* d_in, const int* in_sizes, int n_in,
                              void* d_out, int out_size) {
    const float* x      = (const float*)d_in[0];
    const float* cached = (const float*)d_in[1];
    const float* Wqkv   = (const float*)d_in[2];
    const float* qb     = (const float*)d_in[3];
    const float* vb     = (const float*)d_in[4];
    const float* Wproj  = (const float*)d_in[5];
    const float* bp     = (const float*)d_in[6];
    const float* slog   = (const float*)d_in[7];
    const float* rope   = (const float*)d_in[8];
    float* out = (float*)d_out;

    void *p_qkv, *p_pr, *p_bias, *p_ax, *p_wq, *p_wp, *p_ao;
    cudaGetSymbolAddress(&p_qkv, g_qkv);
    cudaGetSymbolAddress(&p_pr, g_pr);
    cudaGetSymbolAddress(&p_bias, g_bias);
    cudaGetSymbolAddress(&p_ax, g_ax);
    cudaGetSymbolAddress(&p_wq, g_wq);
    cudaGetSymbolAddress(&p_wp, g_wp);
    cudaGetSymbolAddress(&p_ao, g_ao);

    cudaFuncSetAttribute(k_fattn, cudaFuncAttributeMaxDynamicSharedMemorySize, FA_SMEM);

    k_colsum<<<dim3(4, 8, BB), 256>>>(x);
    k_meanfin<<<8, 256>>>();
    k_mse<<<dim3(LL, BB), 256>>>(x);
    k_topk<<<BB, 1024>>>();
    k_bias<<<12, 256>>>(qb, vb);

    // pack split-fp16 operands
    k_splitB<<<(QKVW * CC + 255) / 256, 256>>>(Wqkv, (__half*)p_wq, QKVW * CC);
    k_splitB<<<(CC * CC + 255) / 256, 256>>>(Wproj, (__half*)p_wp, CC * CC);
    k_splitAx<<<(BB * NR * CC + 255) / 256, 256>>>(x, (__half*)p_ax);

    // QKV projection (tensor)
    k_mgemm<<<dim3(QKVW / 128, 13, BB), 256>>>(
        (const __half*)p_ax, (const __half*)p_wq,
        (const float*)p_bias, (float*)p_qkv,
        NR, QKVW, (size_t)NR * GK, (size_t)NR * QKVW);

    k_qkprep<<<dim3(NR, BB), 512>>>(rope, slog);

    // tensor-core flash attention (writes proj A operand directly)
    k_fattn<<<dim3((NR + 127) / 128, NHH, BB), 256, FA_SMEM>>>();

    // output projection (tensor)
    k_mgemm<<<dim3(CC / 128, 13, BB), 256>>>(
        (const __half*)p_ao, (const __half*)p_wp,
        bp, (float*)p_pr,
        NR, CC, (size_t)NR * GK, (size_t)NR * CC);

    k_out1<<<8192, 256>>>(x, cached, out);
    k_out2<<<dim3(NR, BB), 256>>>(x, out);
}

// round 11
// speedup vs baseline: 3.6842x; 1.3226x over previous
#include <cuda_runtime.h>
#include <cuda_fp16.h>
#include <math.h>
#include <stdint.h>

#define BB 2
#define LL 4096
#define CC 1024
#define NHH 16
#define DHH 64
#define NR 1638
#define QKVW 3072
#define GK 1024          // pure fp16 GEMM K (no split)

// ------------------------- scratch (device globals; no runtime alloc) -------
__device__ float g_mean[BB * CC];
__device__ double g_part[BB * 8 * CC];
__device__ float g_mse[BB * LL];
__device__ int g_idx[BB * NR];
__device__ float g_bias[QKVW];
__device__ float g_qkv[(size_t)BB * NR * QKVW];   // (b, i, 3*C) fp32
__device__ float g_pr[(size_t)BB * NR * CC];
// fp16 attention operands
__device__ __half g_qh[(size_t)BB * NHH * NR * DHH];
__device__ __half g_kh[(size_t)BB * NHH * NR * DHH];
__device__ __half g_vh[(size_t)BB * NR * CC];
// fp16 GEMM operands
__device__ __half g_ax[(size_t)BB * NR * GK];   // x[idx] fp16
__device__ __half g_wq[(size_t)QKVW * GK];      // Wqkv fp16
__device__ __half g_wp[(size_t)CC * GK];        // Wproj fp16
__device__ __half g_ao[(size_t)BB * NR * GK];   // attn out fp16 (written by fattn)

// ------------------------- helpers -----------------------------------------
__device__ __forceinline__ float warpSumF(float v) {
#pragma unroll
    for (int m = 16; m; m >>= 1) v += __shfl_xor_sync(0xffffffffu, v, m);
    return v;
}
__device__ __forceinline__ double warpSumD(double v) {
#pragma unroll
    for (int m = 16; m; m >>= 1) v += __shfl_xor_sync(0xffffffffu, v, m);
    return v;
}
__device__ __forceinline__ uint32_t s2u(const void* p) {
    uint32_t a;
    asm("{ .reg .u64 t; cvta.to.shared.u64 t, %1; cvt.u32.u64 %0, t; }" : "=r"(a) : "l"(p));
    return a;
}
__device__ __forceinline__ uint32_t packh(float a, float b) {
    __half2 t = __floats2half2_rn(a, b);   // x=a (low), y=b (high)
    return *(uint32_t*)&t;
}
#define LDSM4(d0, d1, d2, d3, addr) \
    asm volatile("ldmatrix.sync.aligned.m8n8.x4.shared.b16 {%0,%1,%2,%3}, [%4];" \
                 : "=r"(d0), "=r"(d1), "=r"(d2), "=r"(d3) : "r"(addr))
#define LDSM2(d0, d1, addr) \
    asm volatile("ldmatrix.sync.aligned.m8n8.x2.shared.b16 {%0,%1}, [%2];" \
                 : "=r"(d0), "=r"(d1) : "r"(addr))
#define LDSM2T(d0, d1, addr) \
    asm volatile("ldmatrix.sync.aligned.m8n8.x2.trans.shared.b16 {%0,%1}, [%2];" \
                 : "=r"(d0), "=r"(d1) : "r"(addr))
#define MMA16816(c0, c1, c2, c3, a0, a1, a2, a3, b0, b1) \
    asm volatile("mma.sync.aligned.m16n8k16.row.col.f32.f16.f16.f32 " \
                 "{%0,%1,%2,%3}, {%4,%5,%6,%7}, {%8,%9}, {%0,%1,%2,%3};" \
                 : "+f"(c0), "+f"(c1), "+f"(c2), "+f"(c3) \
                 : "r"(a0), "r"(a1), "r"(a2), "r"(a3), "r"(b0), "r"(b1))

// ------------------------- stage 1: mean over L (fp64 accum) ---------------
__global__ void k_colsum(const float* __restrict__ x) {
    int c = blockIdx.x * 256 + threadIdx.x;
    int b = blockIdx.z;
    int l0 = blockIdx.y * 512;
    const float* p = x + ((size_t)b * LL + l0) * CC + c;
    double a0 = 0, a1 = 0, a2 = 0, a3 = 0;
#pragma unroll 4
    for (int l = 0; l < 512; l += 4) {
        a0 += (double)p[(size_t)(l + 0) * CC];
        a1 += (double)p[(size_t)(l + 1) * CC];
        a2 += (double)p[(size_t)(l + 2) * CC];
        a3 += (double)p[(size_t)(l + 3) * CC];
    }
    g_part[(b * 8 + blockIdx.y) * CC + c] = a0 + a1 + a2 + a3;
}

__global__ void k_meanfin() {
    int i = blockIdx.x * 256 + threadIdx.x;
    int b = i >> 10, c = i & 1023;
    double s = 0;
#pragma unroll
    for (int k = 0; k < 8; k++) s += g_part[(b * 8 + k) * CC + c];
    g_mean[b * CC + c] = (float)(s * (1.0 / (double)LL));
}

// ------------------------- stage 2: per-row mse (fp64 accum) ---------------
__global__ void k_mse(const float* __restrict__ x) {
    int l = blockIdx.x, b = blockIdx.y;
    const float* xr = x + ((size_t)b * LL + l) * CC;
    double acc = 0;
#pragma unroll
    for (int k = 0; k < 4; k++) {
        int c = threadIdx.x + k * 256;
        double d = (double)xr[c] - (double)g_mean[b * CC + c];
        acc += d * d;
    }
    acc = warpSumD(acc);
    __shared__ double red[8];
    if ((threadIdx.x & 31) == 0) red[threadIdx.x >> 5] = acc;
    __syncthreads();
    if (threadIdx.x == 0) {
        double t = 0;
#pragma unroll
        for (int w = 0; w < 8; w++) t += red[w];
        g_mse[b * LL + l] = (float)t;
    }
}

// ------------------------- stage 3: top-NR radix select (parallel scan) ----
__global__ void k_topk() {
    __shared__ unsigned int hist[256];
    __shared__ unsigned int suf[256];
    __shared__ unsigned int sh_pref, sh_rank, sh_cgt, sh_ceq;
    int b = blockIdx.x, tid = threadIdx.x;   // 1024 threads
    unsigned int key[4];
#pragma unroll
    for (int k = 0; k < 4; k++)
        key[k] = __float_as_uint(g_mse[b * LL + tid * 4 + k]);  // mse>=0: monotonic bits
    if (tid == 0) { sh_pref = 0; sh_rank = NR; }
#pragma unroll
    for (int pass = 0; pass < 4; pass++) {
        int shift = 24 - pass * 8;
        if (tid < 256) hist[tid] = 0;
        __syncthreads();
        unsigned int pref = sh_pref, r = sh_rank;
        unsigned int himask = (pass == 0) ? 0u : (0xFFFFFFFFu << (shift + 8));
#pragma unroll
        for (int k = 0; k < 4; k++)
            if ((key[k] & himask) == pref)
                atomicAdd(&hist[(key[k] >> shift) & 255], 1u);
        __syncthreads();
        if (tid < 256) suf[tid] = hist[tid];
        __syncthreads();
#pragma unroll
        for (int off = 1; off < 256; off <<= 1) {
            unsigned int t = 0;
            if (tid < 256 && tid + off < 256) t = suf[tid + off];
            __syncthreads();
            if (tid < 256) suf[tid] += t;
            __syncthreads();
        }
        if (tid < 256) {
            unsigned int hi = (tid == 255) ? 0u : suf[tid + 1];
            if (suf[tid] >= r && hi < r) {
                sh_pref = pref | ((unsigned int)tid << shift);
                sh_rank = r - hi;
            }
        }
        __syncthreads();
    }
    if (tid == 0) { sh_cgt = 0; sh_ceq = 0; }
    __syncthreads();
    unsigned int thr = sh_pref, need = sh_rank;
    int ngt = NR - (int)need;
#pragma unroll
    for (int k = 0; k < 4; k++) {
        if (key[k] > thr) {
            unsigned int p = atomicAdd(&sh_cgt, 1u);
            g_idx[b * NR + p] = tid * 4 + k;
        } else if (key[k] == thr) {
            unsigned int p = atomicAdd(&sh_ceq, 1u);
            if (p < need) g_idx[b * NR + ngt + p] = tid * 4 + k;
        }
    }
}

// ------------------------- stage 4: fused bias ------------------------------
__global__ void k_bias(const float* __restrict__ qb, const float* __restrict__ vb) {
    int i = blockIdx.x * 256 + threadIdx.x;
    if (i < QKVW) g_bias[i] = (i < CC) ? qb[i] : ((i < 2 * CC) ? 0.f : vb[i - 2 * CC]);
}

// ------------------------- pack kernels (fp32 -> fp16) ----------------------
__global__ void k_packW(const float* __restrict__ W, __half* __restrict__ out, int total) {
    int i = (blockIdx.x * 256 + threadIdx.x) * 4;
    if (i >= total) return;
    float4 v = *(const float4*)(W + i);
    __half2 a = __floats2half2_rn(v.x, v.y);
    __half2 b = __floats2half2_rn(v.z, v.w);
    *(__half2*)(out + i) = a;
    *(__half2*)(out + i + 2) = b;
}
__global__ void k_packAx(const float* __restrict__ x, __half* __restrict__ out) {
    int i = (blockIdx.x * 256 + threadIdx.x) * 4;
    if (i >= BB * NR * CC) return;
    int c = i & 1023;
    int t = i >> 10;
    int r = t % NR, b = t / NR;
    int li = g_idx[b * NR + r];
    float4 v = *(const float4*)(x + ((size_t)b * LL + li) * CC + c);
    *(__half2*)(out + i) = __floats2half2_rn(v.x, v.y);
    *(__half2*)(out + i + 2) = __floats2half2_rn(v.z, v.w);
}

// ------------------------- tensor GEMM via mma.sync fp16 -------------------
// C(M,N) = A(M,GK) @ B(N,GK)^T + bias.  BM=128 BN=128 BK=32, 8 warps.
#define PITCH 40
#define KITERS (GK / 32)   // 32

__global__ void __launch_bounds__(256, 2) k_mgemm(
    const __half* __restrict__ A, const __half* __restrict__ Bm,
    const float* __restrict__ bias, float* __restrict__ C,
    int M, int N, size_t aBatch, size_t cBatch)
{
    __shared__ __half Asm[2][128 * PITCH];
    __shared__ __half Bsm[2][128 * PITCH];

    int tid = threadIdx.x, wid = tid >> 5, lane = tid & 31;
    int bm = blockIdx.y * 128, bn = blockIdx.x * 128, b = blockIdx.z;
    int wm = wid >> 2, wn = wid & 3;
    const __half* Ab = A + (size_t)b * aBatch;

    int lr = tid >> 1, lc = (tid & 1) * 16;
    bool aok = (bm + lr < M);
    const uint4* aG = (const uint4*)(Ab + (size_t)(aok ? bm + lr : 0) * GK + lc);
    const uint4* bG = (const uint4*)(Bm + (size_t)(bn + lr) * GK + lc);
    const uint32_t BUF = 128 * PITCH * 2;

    uint32_t aL = s2u(&Asm[0][0]) +
                  ((wm * 64 + (lane & 15)) * PITCH + (lane >> 4) * 8) * 2;
    uint32_t bL = s2u(&Bsm[0][0]) +
                  ((wn * 32 + (lane & 7)) * PITCH + ((lane >> 3) & 1) * 8) * 2;

    float acc[4][4][4];
#pragma unroll
    for (int i = 0; i < 4; i++)
#pragma unroll
        for (int j = 0; j < 4; j++)
#pragma unroll
            for (int r = 0; r < 4; r++) acc[i][j][r] = 0.f;

    {
        uint4 a0 = aok ? aG[0] : make_uint4(0, 0, 0, 0);
        uint4 a1 = aok ? aG[1] : make_uint4(0, 0, 0, 0);
        uint4 b0 = bG[0], b1 = bG[1];
        *(uint4*)(Asm[0] + lr * PITCH + lc) = a0;
        *(uint4*)(Asm[0] + lr * PITCH + lc + 8) = a1;
        *(uint4*)(Bsm[0] + lr * PITCH + lc) = b0;
        *(uint4*)(Bsm[0] + lr * PITCH + lc + 8) = b1;
    }
    __syncthreads();

    for (int kt = 0; kt < KITERS; kt++) {
        int s = kt & 1;
        uint4 na0, na1, nb0, nb1;
        bool more = (kt + 1 < KITERS);
        if (more) {
            const uint4* ag = (const uint4*)((const __half*)aG + (kt + 1) * 32);
            const uint4* bg = (const uint4*)((const __half*)bG + (kt + 1) * 32);
            na0 = aok ? ag[0] : make_uint4(0, 0, 0, 0);
            na1 = aok ? ag[1] : make_uint4(0, 0, 0, 0);
            nb0 = bg[0]; nb1 = bg[1];
        }

        uint32_t aBase = aL + s * BUF, bBase = bL + s * BUF;
#pragma unroll
        for (int k16 = 0; k16 < 2; k16++) {
            uint32_t af[4][4], bf[4][2];
#pragma unroll
            for (int i = 0; i < 4; i++)
                LDSM4(af[i][0], af[i][1], af[i][2], af[i][3],
                      aBase + (i * 16 * PITCH + k16 * 16) * 2);
#pragma unroll
            for (int j = 0; j < 4; j++)
                LDSM2(bf[j][0], bf[j][1],
                      bBase + (j * 8 * PITCH + k16 * 16) * 2);
#pragma unroll
            for (int i = 0; i < 4; i++)
#pragma unroll
                for (int j = 0; j < 4; j++)
                    MMA16816(acc[i][j][0], acc[i][j][1], acc[i][j][2], acc[i][j][3],
                             af[i][0], af[i][1], af[i][2], af[i][3],
                             bf[j][0], bf[j][1]);
        }

        if (more) {
            int d = s ^ 1;
            *(uint4*)((char*)(Asm[0] + lr * PITCH + lc) + d * BUF) = na0;
            *(uint4*)((char*)(Asm[0] + lr * PITCH + lc + 8) + d * BUF) = na1;
            *(uint4*)((char*)(Bsm[0] + lr * PITCH + lc) + d * BUF) = nb0;
            *(uint4*)((char*)(Bsm[0] + lr * PITCH + lc + 8) + d * BUF) = nb1;
        }
        __syncthreads();
    }

    float* Cb = C + (size_t)b * cBatch;
    int rq = lane >> 2, cq = (lane & 3) * 2;
#pragma unroll
    for (int i = 0; i < 4; i++) {
#pragma unroll
        for (int j = 0; j < 4; j++) {
            int col = bn + wn * 32 + j * 8 + cq;
            float b0 = bias[col], b1 = bias[col + 1];
            int r0 = bm + wm * 64 + i * 16 + rq;
            if (r0 < M) {
                float2 v = make_float2(acc[i][j][0] + b0, acc[i][j][1] + b1);
                *(float2*)(Cb + (size_t)r0 * N + col) = v;
            }
            if (r0 + 8 < M) {
                float2 v = make_float2(acc[i][j][2] + b0, acc[i][j][3] + b1);
                *(float2*)(Cb + (size_t)(r0 + 8) * N + col) = v;
            }
        }
    }
}

// ------------------------- stage 5: l2norm + scale + rope (-> fp16) --------
__global__ void k_qkprep(const float* __restrict__ rope, const float* __restrict__ slog) {
    int i = blockIdx.x, b = blockIdx.y;
    int h = threadIdx.x >> 5, p = threadIdx.x & 31;
    int li = g_idx[b * NR + i];
    const float* base = g_qkv + ((size_t)b * NR + i) * QKVW;
    float2 q = *(const float2*)(base + h * 64 + 2 * p);
    float2 kk = *(const float2*)(base + CC + h * 64 + 2 * p);
    float2 vv = *(const float2*)(base + 2 * CC + h * 64 + 2 * p);
    float nq = warpSumF(q.x * q.x + q.y * q.y);
    float nk = warpSumF(kk.x * kk.x + kk.y * kk.y);
    float sm = __expf(fminf(slog[h], 4.6051701859880914f));
    float qs = sm / fmaxf(sqrtf(nq), 1e-12f);
    float ks = 1.f / fmaxf(sqrtf(nk), 1e-12f);
    float cv = rope[(size_t)li * 32 + p];
    float sv = rope[(size_t)LL * 32 + (size_t)li * 32 + p];
    float q0 = q.x * qs, q1 = q.y * qs;
    float k0 = kk.x * ks, k1 = kk.y * ks;
    size_t off = (((size_t)b * NHH + h) * NR + i) * DHH + 2 * p;
    *(__half2*)(g_qh + off) = __floats2half2_rn(cv * q0 - sv * q1, sv * q0 + cv * q1);
    *(__half2*)(g_kh + off) = __floats2half2_rn(cv * k0 - sv * k1, sv * k0 + cv * k1);
    *(__half2*)(g_vh + ((size_t)b * NR + i) * CC + h * 64 + 2 * p) =
        __floats2half2_rn(vv.x, vv.y);
}

// ------------------------- stage 6: tensor-core flash attention ------------
// 256 threads, 8 warps, 128 q rows per CTA, 64-kv chunks, fp16 operands.
// Epilogue writes the proj-GEMM A operand (fp16) directly.
#define FAP 72
#define NCHUNK 26
#define FA_SMEM ((128 * FAP + 4 * 64 * FAP) * 2)

__global__ void __launch_bounds__(256, 2) k_fattn() {
    extern __shared__ __half fsm[];
    __half* Qs = fsm;                       // 128 x FAP
    __half* Ks = Qs + 128 * FAP;            // 2 x 64 x FAP
    __half* Vs = Ks + 2 * 64 * FAP;         // 2 x 64 x FAP
    int tid = threadIdx.x, wid = tid >> 5, lane = tid & 31;
    int qbase = blockIdx.x * 128;
    int h = blockIdx.y, b = blockIdx.z;
    const __half* Qg = g_qh + ((size_t)(b * NHH + h)) * NR * DHH;
    const __half* Kg = g_kh + ((size_t)(b * NHH + h)) * NR * DHH;
    const __half* Vg = g_vh + (size_t)b * NR * CC + h * 64;

    const uint4 z4 = make_uint4(0, 0, 0, 0);
    int lrow = tid >> 1, lhalf = tid & 1;     // Q loader: 128 rows x 32-elem half
    int krow = tid >> 2, kq = tid & 3;        // K/V loader: 64 rows x 16-elem quarter

    {   // Q tile
        int qi = qbase + lrow;
        const uint4* src = (const uint4*)(Qg + (size_t)(qi < NR ? qi : 0) * DHH + lhalf * 32);
        uint4* dst = (uint4*)&Qs[lrow * FAP + lhalf * 32];
#pragma unroll
        for (int t = 0; t < 4; t++) dst[t] = (qi < NR) ? src[t] : z4;
    }
    {   // K/V chunk 0
        const uint4* ks = (const uint4*)(Kg + (size_t)krow * DHH + kq * 16);
        const uint4* vs = (const uint4*)(Vg + (size_t)krow * CC + kq * 16);
        uint4* kd = (uint4*)&Ks[krow * FAP + kq * 16];
        uint4* vd = (uint4*)&Vs[krow * FAP + kq * 16];
        kd[0] = ks[0]; kd[1] = ks[1];
        vd[0] = vs[0]; vd[1] = vs[1];
    }
    __syncthreads();

    // persistent Q fragments (warp owns rows qbase + wid*16 .. +15)
    uint32_t qf[4][4];
    uint32_t qaddr = s2u(Qs) + ((wid * 16 + (lane & 15)) * FAP) * 2;
#pragma unroll
    for (int c = 0; c < 4; c++)
        LDSM4(qf[c][0], qf[c][1], qf[c][2], qf[c][3],
              qaddr + (16 * c + (lane >> 4) * 8) * 2);

    float m0 = -1e30f, m1 = -1e30f, l0 = 0.f, l1 = 0.f;
    float o[8][4];
#pragma unroll
    for (int j = 0; j < 8; j++)
#pragma unroll
        for (int r = 0; r < 4; r++) o[j][r] = 0.f;

    for (int kt = 0; kt < NCHUNK; kt++) {
        int s = kt & 1;
        uint4 nk[2], nv[2];
        bool more = (kt + 1 < NCHUNK);
        if (more) {
            int kc = (kt + 1) * 64 + krow;
            bool ok = kc < NR;
            const uint4* ks = (const uint4*)(Kg + (size_t)(ok ? kc : 0) * DHH + kq * 16);
            const uint4* vs = (const uint4*)(Vg + (size_t)(ok ? kc : 0) * CC + kq * 16);
            nk[0] = ok ? ks[0] : z4; nk[1] = ok ? ks[1] : z4;
            nv[0] = ok ? vs[0] : z4; nv[1] = ok ? vs[1] : z4;
        }

        uint32_t kb = s2u(&Ks[s * 64 * FAP]);
        uint32_t vb = s2u(&Vs[s * 64 * FAP]);

        // S = Q K^T
        float sc[8][4];
#pragma unroll
        for (int j = 0; j < 8; j++) {
            sc[j][0] = sc[j][1] = sc[j][2] = sc[j][3] = 0.f;
#pragma unroll
            for (int c = 0; c < 4; c++) {
                uint32_t b0, b1;
                LDSM2(b0, b1, kb + ((8 * j + (lane & 7)) * FAP +
                                    16 * c + ((lane >> 3) & 1) * 8) * 2);
                MMA16816(sc[j][0], sc[j][1], sc[j][2], sc[j][3],
                         qf[c][0], qf[c][1], qf[c][2], qf[c][3], b0, b1);
            }
        }

        // mask (last chunk only)
        if (kt * 64 + 64 > NR) {
#pragma unroll
            for (int j = 0; j < 8; j++) {
                int col = kt * 64 + 8 * j + 2 * (lane & 3);
                if (col >= NR)     { sc[j][0] = -1e30f; sc[j][2] = -1e30f; }
                if (col + 1 >= NR) { sc[j][1] = -1e30f; sc[j][3] = -1e30f; }
            }
        }

        // online softmax
        float rm0 = -1e30f, rm1 = -1e30f;
#pragma unroll
        for (int j = 0; j < 8; j++) {
            rm0 = fmaxf(rm0, fmaxf(sc[j][0], sc[j][1]));
            rm1 = fmaxf(rm1, fmaxf(sc[j][2], sc[j][3]));
        }
        rm0 = fmaxf(rm0, __shfl_xor_sync(0xffffffffu, rm0, 1));
        rm0 = fmaxf(rm0, __shfl_xor_sync(0xffffffffu, rm0, 2));
        rm1 = fmaxf(rm1, __shfl_xor_sync(0xffffffffu, rm1, 1));
        rm1 = fmaxf(rm1, __shfl_xor_sync(0xffffffffu, rm1, 2));
        float mn0 = fmaxf(m0, rm0), mn1 = fmaxf(m1, rm1);
        float cr0 = __expf(m0 - mn0), cr1 = __expf(m1 - mn1);
        m0 = mn0; m1 = mn1;
        float s0 = 0.f, s1 = 0.f;
#pragma unroll
        for (int j = 0; j < 8; j++) {
            sc[j][0] = __expf(sc[j][0] - mn0);
            sc[j][1] = __expf(sc[j][1] - mn0);
            sc[j][2] = __expf(sc[j][2] - mn1);
            sc[j][3] = __expf(sc[j][3] - mn1);
            s0 += sc[j][0] + sc[j][1];
            s1 += sc[j][2] + sc[j][3];
        }
        s0 += __shfl_xor_sync(0xffffffffu, s0, 1);
        s0 += __shfl_xor_sync(0xffffffffu, s0, 2);
        s1 += __shfl_xor_sync(0xffffffffu, s1, 1);
        s1 += __shfl_xor_sync(0xffffffffu, s1, 2);
        l0 = l0 * cr0 + s0;
        l1 = l1 * cr1 + s1;
#pragma unroll
        for (int j = 0; j < 8; j++) {
            o[j][0] *= cr0; o[j][1] *= cr0;
            o[j][2] *= cr1; o[j][3] *= cr1;
        }

        // repack P -> A fragments
        uint32_t pa[4][4];
#pragma unroll
        for (int c = 0; c < 4; c++) {
            pa[c][0] = packh(sc[2 * c][0], sc[2 * c][1]);
            pa[c][1] = packh(sc[2 * c][2], sc[2 * c][3]);
            pa[c][2] = packh(sc[2 * c + 1][0], sc[2 * c + 1][1]);
            pa[c][3] = packh(sc[2 * c + 1][2], sc[2 * c + 1][3]);
        }

        // O += P V
#pragma unroll
        for (int j = 0; j < 8; j++) {
#pragma unroll
            for (int c = 0; c < 4; c++) {
                uint32_t b0, b1;
                LDSM2T(b0, b1, vb + ((16 * c + (lane & 15)) * FAP + 8 * j) * 2);
                MMA16816(o[j][0], o[j][1], o[j][2], o[j][3],
                         pa[c][0], pa[c][1], pa[c][2], pa[c][3], b0, b1);
            }
        }

        if (more) {
            int d = s ^ 1;
            uint4* kd = (uint4*)&Ks[d * 64 * FAP + krow * FAP + kq * 16];
            uint4* vd = (uint4*)&Vs[d * 64 * FAP + krow * FAP + kq * 16];
            kd[0] = nk[0]; kd[1] = nk[1];
            vd[0] = nv[0]; vd[1] = nv[1];
        }
        __syncthreads();
    }

    // epilogue: write proj A operand fp16 directly
    int r0 = qbase + wid * 16 + (lane >> 2);
    float inv0 = 1.f / l0, inv1 = 1.f / l1;
#pragma unroll
    for (int j = 0; j < 8; j++) {
        int col = h * 64 + 8 * j + 2 * (lane & 3);
#pragma unroll
        for (int half = 0; half < 2; half++) {
            int r = r0 + half * 8;
            if (r >= NR) continue;
            float va = o[j][2 * half + 0] * (half ? inv1 : inv0);
            float vbv = o[j][2 * half + 1] * (half ? inv1 : inv0);
            *(__half2*)&g_ao[((size_t)b * NR + r) * GK + col] =
                __floats2half2_rn(va, vbv);
        }
    }
}

// ------------------------- stage 7: residual + upsample + scatter ----------
__global__ void k_out1(const float* __restrict__ x, const float* __restrict__ cached,
                       float* __restrict__ out) {
    size_t e = ((size_t)blockIdx.x * 256 + threadIdx.x) * 4;
    int b = (int)(e >> 22);
    int rem = (int)(e & ((1u << 22) - 1));
    int l = rem >> 10, c = rem & 1023;
    int hh = l >> 6, ww = l & 63;
    size_t uoff = ((((size_t)b * 32 + (hh >> 1)) * 32) + (ww >> 1)) * 1024 + c;
    float4 xv = *(const float4*)(x + e);
    float4 uv = *(const float4*)(cached + uoff);
    *(float4*)(out + e) = make_float4(xv.x + uv.x, xv.y + uv.y, xv.z + uv.z, xv.w + uv.w);
}

__global__ void k_out2(const float* __restrict__ x, float* __restrict__ out) {
    int i = blockIdx.x, b = blockIdx.y;
    int li = g_idx[b * NR + i];
    int c = threadIdx.x * 4;
    size_t xoff = ((size_t)b * LL + li) * CC + c;
    float4 xv = *(const float4*)(x + xoff);
    float4 pv = *(const float4*)(g_pr + ((size_t)b * NR + i) * CC + c);
    *(float4*)(out + xoff) = make_float4(xv.x + pv.x, xv.y + pv.y, xv.z + pv.z, xv.w + pv.w);
}

// ------------------------- launcher ----------------------------------------
extern "C" void kernel_launch(void* const* d_in, const int* in_sizes, int n_in,
                              void* d_out, int out_size) {
    const float* x      = (const float*)d_in[0];
    const float* cached = (const float*)d_in[1];
    const float* Wqkv   = (const float*)d_in[2];
    const float* qb     = (const float*)d_in[3];
    const float* vb     = (const float*)d_in[4];
    const float* Wproj  = (const float*)d_in[5];
    const float* bp     = (const float*)d_in[6];
    const float* slog   = (const float*)d_in[7];
    const float* rope   = (const float*)d_in[8];
    float* out = (float*)d_out;

    void *p_qkv, *p_pr, *p_bias, *p_ax, *p_wq, *p_wp, *p_ao;
    cudaGetSymbolAddress(&p_qkv, g_qkv);
    cudaGetSymbolAddress(&p_pr, g_pr);
    cudaGetSymbolAddress(&p_bias, g_bias);
    cudaGetSymbolAddress(&p_ax, g_ax);
    cudaGetSymbolAddress(&p_wq, g_wq);
    cudaGetSymbolAddress(&p_wp, g_wp);
    cudaGetSymbolAddress(&p_ao, g_ao);

    cudaFuncSetAttribute(k_fattn, cudaFuncAttributeMaxDynamicSharedMemorySize, FA_SMEM);

    k_colsum<<<dim3(4, 8, BB), 256>>>(x);
    k_meanfin<<<8, 256>>>();
    k_mse<<<dim3(LL, BB), 256>>>(x);
    k_topk<<<BB, 1024>>>();
    k_bias<<<12, 256>>>(qb, vb);

    // pack fp16 operands
    k_packW<<<(QKVW * CC / 4 + 255) / 256, 256>>>(Wqkv, (__half*)p_wq, QKVW * CC);
    k_packW<<<(CC * CC / 4 + 255) / 256, 256>>>(Wproj, (__half*)p_wp, CC * CC);
    k_packAx<<<(BB * NR * CC / 4 + 255) / 256, 256>>>(x, (__half*)p_ax);

    // QKV projection (tensor, fp16 K=1024)
    k_mgemm<<<dim3(QKVW / 128, 13, BB), 256>>>(
        (const __half*)p_ax, (const __half*)p_wq,
        (const float*)p_bias, (float*)p_qkv,
        NR, QKVW, (size_t)NR * GK, (size_t)NR * QKVW);

    k_qkprep<<<dim3(NR, BB), 512>>>(rope, slog);

    // tensor-core flash attention (writes proj A operand directly)
    k_fattn<<<dim3((NR + 127) / 128, NHH, BB), 256, FA_SMEM>>>();

    // output projection (tensor, fp16 K=1024)
    k_mgemm<<<dim3(CC / 128, 13, BB), 256>>>(
        (const __half*)p_ao, (const __half*)p_wp,
        bp, (float*)p_pr,
        NR, CC, (size_t)NR * GK, (size_t)NR * CC);

    k_out1<<<8192, 256>>>(x, cached, out);
    k_out2<<<dim3(NR, BB), 256>>>(x, out);
}